// round 1
// baseline (speedup 1.0000x reference)
#include <cuda_runtime.h>

#define N_NODES 100000
#define N_EDGES 1600000
#define TOT_E   (N_EDGES + N_NODES)   // 1,700,000 (edges + self loops)
#define F_IN    128
#define HEADS   8
#define HID     8
#define HC      64                    // HEADS*HID
#define NCLS    40
#define NEG_SLOPE 0.2f
#define FNEG_MAX  -3.402823466e38f

// ---------------- scratch (static device globals; no allocation allowed) ----
__device__ __align__(16) float g_h1 [N_NODES * HC];     // layer1 GEMM out
__device__ __align__(16) float g_o1 [N_NODES * HC];     // layer1 num-accum -> activated feature
__device__ float g_as1[N_NODES * HEADS];
__device__ float g_ad1[N_NODES * HEADS];
__device__ float g_m1 [N_NODES * HEADS];
__device__ float g_dn1[N_NODES * HEADS];
__device__ __align__(16) float g_h2 [N_NODES * NCLS];
__device__ float g_as2[N_NODES];
__device__ float g_ad2[N_NODES];
__device__ float g_m2 [N_NODES];
__device__ float g_dn2[N_NODES];
__device__ int   g_is64;

// ---------------- helpers ---------------------------------------------------
__device__ __forceinline__ float lrelu(float x) { return x > 0.f ? x : NEG_SLOPE * x; }

__device__ __forceinline__ void atomicMaxF(float* a, float v) {
    if (v >= 0.f) atomicMax((int*)a, __float_as_int(v));
    else          atomicMin((unsigned int*)a, __float_as_uint(v));
}

// edge_index may arrive as int64 (reference dtype) or int32 (jax w/o x64).
__global__ void probe_dtype(const long long* __restrict__ ei) {
    if (blockIdx.x == 0 && threadIdx.x == 0) {
        int ok = 1;
        for (int k = 0; k < 256; k++) {
            long long v = ei[k];
            if (v < 0 || v >= (long long)N_NODES) { ok = 0; break; }
        }
        g_is64 = ok;
    }
}

__device__ __forceinline__ void load_edge(const void* __restrict__ ei, unsigned e,
                                          int& s, int& d) {
    if (e < (unsigned)N_EDGES) {
        if (g_is64) {
            const long long* p = (const long long*)ei;
            s = (int)p[e]; d = (int)p[N_EDGES + e];
        } else {
            const int* p = (const int*)ei;
            s = p[e]; d = p[N_EDGES + e];
        }
    } else {
        s = d = (int)(e - (unsigned)N_EDGES);   // self loop
    }
}

// ---------------- init ------------------------------------------------------
__global__ void init1() {
    unsigned i = blockIdx.x * 256u + threadIdx.x;
    if (i < N_NODES * HC) g_o1[i] = 0.f;
    if (i < N_NODES * HEADS) { g_dn1[i] = 0.f; g_m1[i] = FNEG_MAX; }
}

__global__ void init2(float* __restrict__ out) {
    unsigned i = blockIdx.x * 256u + threadIdx.x;
    if (i < N_NODES * NCLS) out[i] = 0.f;
    if (i < N_NODES) { g_dn2[i] = 0.f; g_m2[i] = FNEG_MAX; }
}

// ---------------- layer 1 GEMM + attention logits ---------------------------
// block = 256 thr = 8 warps; each warp handles 4 nodes; block handles 32 nodes.
__global__ void __launch_bounds__(256) gemm1(const float* __restrict__ x,
                                             const float* __restrict__ W,
                                             const float* __restrict__ asrc,
                                             const float* __restrict__ adst) {
    __shared__ float  Ws[F_IN * HC];        // 32 KB
    __shared__ float4 xs[8][F_IN];          // 16 KB
    __shared__ float  as_s[HC], ad_s[HC];

    int tid = threadIdx.x;
    for (int i = tid; i < F_IN * HC; i += 256) Ws[i] = W[i];
    if (tid < HC) { as_s[tid] = asrc[tid]; ad_s[tid] = adst[tid]; }

    int warp = tid >> 5, lane = tid & 31;
    int n0 = blockIdx.x * 32 + warp * 4;    // N_NODES % 32 == 0, no guards

    for (int k = lane; k < F_IN; k += 32) {
        float4 v;
        v.x = x[(n0 + 0) * F_IN + k];
        v.y = x[(n0 + 1) * F_IN + k];
        v.z = x[(n0 + 2) * F_IN + k];
        v.w = x[(n0 + 3) * F_IN + k];
        xs[warp][k] = v;
    }
    __syncthreads();

    float a00 = 0, a01 = 0, a10 = 0, a11 = 0, a20 = 0, a21 = 0, a30 = 0, a31 = 0;
    const float2* W2p = (const float2*)Ws;
#pragma unroll 8
    for (int k = 0; k < F_IN; k++) {
        float4 xv = xs[warp][k];
        float2 wv = W2p[k * 32 + lane];
        a00 += xv.x * wv.x; a01 += xv.x * wv.y;
        a10 += xv.y * wv.x; a11 += xv.y * wv.y;
        a20 += xv.z * wv.x; a21 += xv.z * wv.y;
        a30 += xv.w * wv.x; a31 += xv.w * wv.y;
    }

    int j0 = lane * 2;
    float asx = as_s[j0], asy = as_s[j0 + 1];
    float adx = ad_s[j0], ady = ad_s[j0 + 1];

#define EMIT(E, A0, A1)                                                          \
    {                                                                            \
        int n = n0 + (E);                                                        \
        g_h1[n * HC + j0] = (A0); g_h1[n * HC + j0 + 1] = (A1);                  \
        float ps = (A0) * asx + (A1) * asy;                                      \
        float pd = (A0) * adx + (A1) * ady;                                      \
        ps += __shfl_xor_sync(0xffffffffu, ps, 1);                               \
        ps += __shfl_xor_sync(0xffffffffu, ps, 2);                               \
        pd += __shfl_xor_sync(0xffffffffu, pd, 1);                               \
        pd += __shfl_xor_sync(0xffffffffu, pd, 2);                               \
        if ((lane & 3) == 0) {                                                   \
            g_as1[n * HEADS + (lane >> 2)] = ps;                                 \
            g_ad1[n * HEADS + (lane >> 2)] = pd;                                 \
        }                                                                        \
    }
    EMIT(0, a00, a01) EMIT(1, a10, a11) EMIT(2, a20, a21) EMIT(3, a30, a31)
#undef EMIT
}

// ---------------- layer 1 edge passes ---------------------------------------
__global__ void edge_max1(const void* __restrict__ ei) {
    unsigned i = blockIdx.x * 256u + threadIdx.x;
    if (i >= (unsigned)TOT_E * 8u) return;
    unsigned h = i & 7u, e = i >> 3;
    int s, d; load_edge(ei, e, s, d);
    float v = lrelu(g_as1[s * 8 + h] + g_ad1[d * 8 + h]);
    atomicMaxF(&g_m1[d * 8 + h], v);
}

__global__ void edge_acc1(const void* __restrict__ ei) {
    unsigned i = blockIdx.x * 256u + threadIdx.x;
    if (i >= (unsigned)TOT_E * 8u) return;
    unsigned h = i & 7u, e = i >> 3;
    int s, d; load_edge(ei, e, s, d);
    float v  = lrelu(g_as1[s * 8 + h] + g_ad1[d * 8 + h]);
    float ex = __expf(v - g_m1[d * 8 + h]);
    atomicAdd(&g_dn1[d * 8 + h], ex);
    const float4* hp = (const float4*)&g_h1[s * HC + h * 8];
    float4 h0 = hp[0], h1 = hp[1];
    float* od = &g_o1[d * HC + h * 8];
    asm volatile("red.global.add.v4.f32 [%0], {%1,%2,%3,%4};" ::
                 "l"(od), "f"(ex * h0.x), "f"(ex * h0.y), "f"(ex * h0.z), "f"(ex * h0.w)
                 : "memory");
    asm volatile("red.global.add.v4.f32 [%0], {%1,%2,%3,%4};" ::
                 "l"(od + 4), "f"(ex * h1.x), "f"(ex * h1.y), "f"(ex * h1.z), "f"(ex * h1.w)
                 : "memory");
}

__global__ void finalize1(const float* __restrict__ b1) {
    unsigned i = blockIdx.x * 256u + threadIdx.x;
    if (i >= N_NODES * HC) return;
    unsigned n = i >> 6, j = i & 63u, h = j >> 3;
    float v = g_o1[i] / (g_dn1[n * 8 + h] + 1e-16f) + b1[j];
    g_o1[i] = fmaxf(v, 0.f);                // ReLU between layers
}

// ---------------- layer 2 GEMM + attention logits ---------------------------
// block = 256 thr = 8 warps; one node per warp.
__global__ void __launch_bounds__(256) gemm2(const float* __restrict__ W2,
                                             const float* __restrict__ as2,
                                             const float* __restrict__ ad2) {
    __shared__ float Ws[HC * NCLS];         // 10 KB
    __shared__ float hs[8][HC];
    __shared__ float a2s[NCLS], a2d[NCLS];

    int tid = threadIdx.x;
    for (int i = tid; i < HC * NCLS; i += 256) Ws[i] = W2[i];
    if (tid < NCLS) { a2s[tid] = as2[tid]; a2d[tid] = ad2[tid]; }

    int warp = tid >> 5, lane = tid & 31;
    int n = blockIdx.x * 8 + warp;          // N_NODES % 8 == 0
    hs[warp][lane]      = g_o1[n * HC + lane];
    hs[warp][lane + 32] = g_o1[n * HC + lane + 32];
    __syncthreads();

    float acc0 = 0.f, acc1 = 0.f;
    int l8 = 32 + (lane & 7);               // safe index; result used only if lane<8
#pragma unroll 8
    for (int k = 0; k < HC; k++) {
        float hv = hs[warp][k];
        acc0 += hv * Ws[k * NCLS + lane];
        acc1 += hv * Ws[k * NCLS + l8];
    }

    g_h2[n * NCLS + lane] = acc0;
    if (lane < 8) g_h2[n * NCLS + 32 + lane] = acc1;

    float ps = acc0 * a2s[lane] + (lane < 8 ? acc1 * a2s[32 + lane] : 0.f);
    float pd = acc0 * a2d[lane] + (lane < 8 ? acc1 * a2d[32 + lane] : 0.f);
#pragma unroll
    for (int o = 16; o; o >>= 1) {
        ps += __shfl_xor_sync(0xffffffffu, ps, o);
        pd += __shfl_xor_sync(0xffffffffu, pd, o);
    }
    if (lane == 0) { g_as2[n] = ps; g_ad2[n] = pd; }
}

// ---------------- layer 2 edge passes ---------------------------------------
__global__ void edge_max2(const void* __restrict__ ei) {
    unsigned e = blockIdx.x * 256u + threadIdx.x;
    if (e >= (unsigned)TOT_E) return;
    int s, d; load_edge(ei, e, s, d);
    float v = lrelu(g_as2[s] + g_ad2[d]);
    atomicMaxF(&g_m2[d], v);
}

// 10 threads per edge; thread t handles classes [4t, 4t+4) with a vector RED.
__global__ void edge_acc2(const void* __restrict__ ei, float* __restrict__ out) {
    unsigned i = blockIdx.x * 256u + threadIdx.x;
    if (i >= (unsigned)TOT_E * 10u) return;
    unsigned t = i % 10u, e = i / 10u;
    int s, d; load_edge(ei, e, s, d);
    float v  = lrelu(g_as2[s] + g_ad2[d]);
    float ex = __expf(v - g_m2[d]);
    if (t == 0) atomicAdd(&g_dn2[d], ex);
    float4 hv = *(const float4*)&g_h2[s * NCLS + t * 4];
    float* od = &out[d * NCLS + t * 4];
    asm volatile("red.global.add.v4.f32 [%0], {%1,%2,%3,%4};" ::
                 "l"(od), "f"(ex * hv.x), "f"(ex * hv.y), "f"(ex * hv.z), "f"(ex * hv.w)
                 : "memory");
}

__global__ void finalize2(float* __restrict__ out, const float* __restrict__ b2) {
    unsigned i = blockIdx.x * 256u + threadIdx.x;
    if (i >= N_NODES * NCLS) return;
    unsigned n = i / NCLS, c = i % NCLS;
    out[i] = out[i] / (g_dn2[n] + 1e-16f) + b2[c];
}

// ---------------- launch -----------------------------------------------------
extern "C" void kernel_launch(void* const* d_in, const int* in_sizes, int n_in,
                              void* d_out, int out_size) {
    const float*     x   = (const float*)d_in[0];
    const void*      ei  = d_in[1];                  // int64 or int32, probed
    const float*     W1  = (const float*)d_in[2];
    const float*     as1 = (const float*)d_in[3];
    const float*     ad1 = (const float*)d_in[4];
    const float*     b1  = (const float*)d_in[5];
    const float*     W2  = (const float*)d_in[6];
    const float*     as2 = (const float*)d_in[7];
    const float*     ad2 = (const float*)d_in[8];
    const float*     b2  = (const float*)d_in[9];
    float*           out = (float*)d_out;

    probe_dtype<<<1, 32>>>((const long long*)ei);

    // ---- layer 1 ----
    init1<<<(N_NODES * HC + 255) / 256, 256>>>();
    gemm1<<<N_NODES / 32, 256>>>(x, W1, as1, ad1);
    edge_max1<<<((unsigned)TOT_E * 8u + 255) / 256, 256>>>(ei);
    edge_acc1<<<((unsigned)TOT_E * 8u + 255) / 256, 256>>>(ei);
    finalize1<<<(N_NODES * HC + 255) / 256, 256>>>(b1);

    // ---- layer 2 ----
    init2<<<(N_NODES * NCLS + 255) / 256, 256>>>(out);
    gemm2<<<N_NODES / 8, 256>>>(W2, as2, ad2);
    edge_max2<<<((unsigned)TOT_E + 255) / 256, 256>>>(ei);
    edge_acc2<<<((unsigned)TOT_E * 10u + 255) / 256, 256>>>(ei, out);
    finalize2<<<(N_NODES * NCLS + 255) / 256, 256>>>(out, b2);
}

// round 2
// speedup vs baseline: 1.2071x; 1.2071x over previous
#include <cuda_runtime.h>

#define N_NODES 100000
#define N_EDGES 1600000
#define TOT_E   (N_EDGES + N_NODES)   // 1,700,000 (edges + self loops)
#define F_IN    128
#define HEADS   8
#define HID     8
#define HC      64                    // HEADS*HID
#define NCLS    40
#define NEG_SLOPE 0.2f

// ---------------- scratch (static device globals; no allocation allowed) ----
__device__ __align__(16) float g_h1 [N_NODES * HC];     // layer1 GEMM out
__device__ __align__(16) float g_o1 [N_NODES * HC];     // layer1 accum -> activated feature
__device__ float g_as1[N_NODES * HEADS];
__device__ float g_ad1[N_NODES * HEADS];
__device__ float g_dn1[N_NODES * HEADS];
__device__ __align__(16) float g_h2 [N_NODES * NCLS];
__device__ float g_as2[N_NODES];
__device__ float g_ad2[N_NODES];
__device__ float g_dn2[N_NODES];
__device__ __align__(8) int2  g_edge[TOT_E];            // decoded (src, dst)
__device__ int   g_is64;

// ---------------- helpers ---------------------------------------------------
__device__ __forceinline__ float lrelu(float x) { return x > 0.f ? x : NEG_SLOPE * x; }

// edge_index may arrive as int64 (reference dtype) or int32 (jax w/o x64).
__global__ void probe_dtype(const long long* __restrict__ ei) {
    if (blockIdx.x == 0 && threadIdx.x == 0) {
        int ok = 1;
        for (int k = 0; k < 256; k++) {
            long long v = ei[k];
            if (v < 0 || v >= (long long)N_NODES) { ok = 0; break; }
        }
        g_is64 = ok;
    }
}

// Decode edge list once (plus self loops) into coalesced int2.
__global__ void decode_edges(const void* __restrict__ ei) {
    unsigned e = blockIdx.x * 256u + threadIdx.x;
    if (e >= (unsigned)TOT_E) return;
    int s, d;
    if (e < (unsigned)N_EDGES) {
        if (g_is64) {
            const long long* p = (const long long*)ei;
            s = (int)p[e]; d = (int)p[N_EDGES + e];
        } else {
            const int* p = (const int*)ei;
            s = p[e]; d = p[N_EDGES + e];
        }
    } else {
        s = d = (int)(e - (unsigned)N_EDGES);
    }
    g_edge[e] = make_int2(s, d);
}

// ---------------- layer 1 GEMM + attention logits + accumulator init --------
// block = 256 thr = 8 warps; each warp handles 4 nodes; block handles 32 nodes.
__global__ void __launch_bounds__(256) gemm1(const float* __restrict__ x,
                                             const float* __restrict__ W,
                                             const float* __restrict__ asrc,
                                             const float* __restrict__ adst) {
    __shared__ float  Ws[F_IN * HC];        // 32 KB
    __shared__ float4 xs[8][F_IN];          // 16 KB
    __shared__ float  as_s[HC], ad_s[HC];

    int tid = threadIdx.x;
    for (int i = tid; i < F_IN * HC; i += 256) Ws[i] = W[i];
    if (tid < HC) { as_s[tid] = asrc[tid]; ad_s[tid] = adst[tid]; }

    int warp = tid >> 5, lane = tid & 31;
    int n0 = blockIdx.x * 32 + warp * 4;    // N_NODES % 32 == 0, no guards

    for (int k = lane; k < F_IN; k += 32) {
        float4 v;
        v.x = x[(n0 + 0) * F_IN + k];
        v.y = x[(n0 + 1) * F_IN + k];
        v.z = x[(n0 + 2) * F_IN + k];
        v.w = x[(n0 + 3) * F_IN + k];
        xs[warp][k] = v;
    }
    __syncthreads();

    float a00 = 0, a01 = 0, a10 = 0, a11 = 0, a20 = 0, a21 = 0, a30 = 0, a31 = 0;
    const float2* W2p = (const float2*)Ws;
#pragma unroll 8
    for (int k = 0; k < F_IN; k++) {
        float4 xv = xs[warp][k];
        float2 wv = W2p[k * 32 + lane];
        a00 += xv.x * wv.x; a01 += xv.x * wv.y;
        a10 += xv.y * wv.x; a11 += xv.y * wv.y;
        a20 += xv.z * wv.x; a21 += xv.z * wv.y;
        a30 += xv.w * wv.x; a31 += xv.w * wv.y;
    }

    int j0 = lane * 2;
    float asx = as_s[j0], asy = as_s[j0 + 1];
    float adx = ad_s[j0], ady = ad_s[j0 + 1];

#define EMIT(E, A0, A1)                                                          \
    {                                                                            \
        int n = n0 + (E);                                                        \
        g_h1[n * HC + j0] = (A0); g_h1[n * HC + j0 + 1] = (A1);                  \
        g_o1[n * HC + j0] = 0.f;  g_o1[n * HC + j0 + 1] = 0.f;                   \
        float ps = (A0) * asx + (A1) * asy;                                      \
        float pd = (A0) * adx + (A1) * ady;                                      \
        ps += __shfl_xor_sync(0xffffffffu, ps, 1);                               \
        ps += __shfl_xor_sync(0xffffffffu, ps, 2);                               \
        pd += __shfl_xor_sync(0xffffffffu, pd, 1);                               \
        pd += __shfl_xor_sync(0xffffffffu, pd, 2);                               \
        if ((lane & 3) == 0) {                                                   \
            g_as1[n * HEADS + (lane >> 2)] = ps;                                 \
            g_ad1[n * HEADS + (lane >> 2)] = pd;                                 \
            g_dn1[n * HEADS + (lane >> 2)] = 0.f;                                \
        }                                                                        \
    }
    EMIT(0, a00, a01) EMIT(1, a10, a11) EMIT(2, a20, a21) EMIT(3, a30, a31)
#undef EMIT
}

// ---------------- layer 1 fused edge pass (no max subtraction) --------------
// 8 threads per edge, one per head.
__global__ void edge_acc1() {
    unsigned i = blockIdx.x * 256u + threadIdx.x;
    if (i >= (unsigned)TOT_E * 8u) return;
    unsigned h = i & 7u, e = i >> 3;
    int2 ed = g_edge[e];
    float v  = lrelu(g_as1[ed.x * 8 + h] + g_ad1[ed.y * 8 + h]);
    float ex = __expf(v);
    atomicAdd(&g_dn1[ed.y * 8 + h], ex);
    const float4* hp = (const float4*)&g_h1[ed.x * HC + h * 8];
    float4 h0 = hp[0], h1 = hp[1];
    float* od = &g_o1[ed.y * HC + h * 8];
    asm volatile("red.global.add.v4.f32 [%0], {%1,%2,%3,%4};" ::
                 "l"(od), "f"(ex * h0.x), "f"(ex * h0.y), "f"(ex * h0.z), "f"(ex * h0.w)
                 : "memory");
    asm volatile("red.global.add.v4.f32 [%0], {%1,%2,%3,%4};" ::
                 "l"(od + 4), "f"(ex * h1.x), "f"(ex * h1.y), "f"(ex * h1.z), "f"(ex * h1.w)
                 : "memory");
}

__global__ void finalize1(const float* __restrict__ b1) {
    unsigned i = blockIdx.x * 256u + threadIdx.x;
    if (i >= N_NODES * HC) return;
    unsigned n = i >> 6, j = i & 63u, h = j >> 3;
    float v = g_o1[i] / (g_dn1[n * 8 + h] + 1e-16f) + b1[j];
    g_o1[i] = fmaxf(v, 0.f);                // ReLU between layers
}

// ---------------- layer 2 GEMM + attention logits + accumulator init --------
// block = 256 thr = 8 warps; one node per warp.
__global__ void __launch_bounds__(256) gemm2(const float* __restrict__ W2,
                                             const float* __restrict__ as2,
                                             const float* __restrict__ ad2,
                                             float* __restrict__ out) {
    __shared__ float Ws[HC * NCLS];         // 10 KB
    __shared__ float hs[8][HC];
    __shared__ float a2s[NCLS], a2d[NCLS];

    int tid = threadIdx.x;
    for (int i = tid; i < HC * NCLS; i += 256) Ws[i] = W2[i];
    if (tid < NCLS) { a2s[tid] = as2[tid]; a2d[tid] = ad2[tid]; }

    int warp = tid >> 5, lane = tid & 31;
    int n = blockIdx.x * 8 + warp;          // N_NODES % 8 == 0
    hs[warp][lane]      = g_o1[n * HC + lane];
    hs[warp][lane + 32] = g_o1[n * HC + lane + 32];
    __syncthreads();

    float acc0 = 0.f, acc1 = 0.f;
    int l8 = 32 + (lane & 7);               // safe index; result used only if lane<8
#pragma unroll 8
    for (int k = 0; k < HC; k++) {
        float hv = hs[warp][k];
        acc0 += hv * Ws[k * NCLS + lane];
        acc1 += hv * Ws[k * NCLS + l8];
    }

    g_h2[n * NCLS + lane] = acc0;
    out [n * NCLS + lane] = 0.f;
    if (lane < 8) {
        g_h2[n * NCLS + 32 + lane] = acc1;
        out [n * NCLS + 32 + lane] = 0.f;
    }

    float ps = acc0 * a2s[lane] + (lane < 8 ? acc1 * a2s[32 + lane] : 0.f);
    float pd = acc0 * a2d[lane] + (lane < 8 ? acc1 * a2d[32 + lane] : 0.f);
#pragma unroll
    for (int o = 16; o; o >>= 1) {
        ps += __shfl_xor_sync(0xffffffffu, ps, o);
        pd += __shfl_xor_sync(0xffffffffu, pd, o);
    }
    if (lane == 0) { g_as2[n] = ps; g_ad2[n] = pd; g_dn2[n] = 0.f; }
}

// ---------------- layer 2 fused edge pass ------------------------------------
// 3 edges per warp (lanes 0..29); lanes grouped in 10 per edge, thread t
// handles classes [4t, 4t+4). One exp per edge (group leader), broadcast.
__global__ void edge_acc2(float* __restrict__ out) {
    unsigned gw  = (blockIdx.x * 256u + threadIdx.x) >> 5;   // global warp
    int lane = threadIdx.x & 31;
    if (lane >= 30) return;
    unsigned e = gw * 3u + (unsigned)(lane / 10);
    int t = lane % 10;
    bool valid = e < (unsigned)TOT_E;
    unsigned ec = valid ? e : (unsigned)(TOT_E - 1);
    int2 ed = g_edge[ec];
    float ex = 0.f;
    if (t == 0) ex = __expf(lrelu(g_as2[ed.x] + g_ad2[ed.y]));
    ex = __shfl_sync(0x3fffffffu, ex, (lane / 10) * 10);
    if (!valid) return;
    if (t == 0) atomicAdd(&g_dn2[ed.y], ex);
    float4 hv = *(const float4*)&g_h2[ed.x * NCLS + t * 4];
    float* od = &out[ed.y * NCLS + t * 4];
    asm volatile("red.global.add.v4.f32 [%0], {%1,%2,%3,%4};" ::
                 "l"(od), "f"(ex * hv.x), "f"(ex * hv.y), "f"(ex * hv.z), "f"(ex * hv.w)
                 : "memory");
}

__global__ void finalize2(float* __restrict__ out, const float* __restrict__ b2) {
    unsigned i = blockIdx.x * 256u + threadIdx.x;
    if (i >= N_NODES * NCLS) return;
    unsigned n = i / NCLS, c = i % NCLS;
    out[i] = out[i] / (g_dn2[n] + 1e-16f) + b2[c];
}

// ---------------- launch -----------------------------------------------------
extern "C" void kernel_launch(void* const* d_in, const int* in_sizes, int n_in,
                              void* d_out, int out_size) {
    const float*     x   = (const float*)d_in[0];
    const void*      ei  = d_in[1];                  // int64 or int32, probed
    const float*     W1  = (const float*)d_in[2];
    const float*     as1 = (const float*)d_in[3];
    const float*     ad1 = (const float*)d_in[4];
    const float*     b1  = (const float*)d_in[5];
    const float*     W2  = (const float*)d_in[6];
    const float*     as2 = (const float*)d_in[7];
    const float*     ad2 = (const float*)d_in[8];
    const float*     b2  = (const float*)d_in[9];
    float*           out = (float*)d_out;

    probe_dtype<<<1, 32>>>((const long long*)ei);
    decode_edges<<<((unsigned)TOT_E + 255) / 256, 256>>>(ei);

    // ---- layer 1 ----
    gemm1<<<N_NODES / 32, 256>>>(x, W1, as1, ad1);
    edge_acc1<<<((unsigned)TOT_E * 8u + 255) / 256, 256>>>();
    finalize1<<<(N_NODES * HC + 255) / 256, 256>>>(b1);

    // ---- layer 2 ----
    gemm2<<<N_NODES / 8, 256>>>(W2, as2, ad2, out);
    unsigned nwarp2 = ((unsigned)TOT_E + 2u) / 3u;
    edge_acc2<<<(nwarp2 * 32u + 255) / 256, 256>>>(out);
    finalize2<<<(N_NODES * NCLS + 255) / 256, 256>>>(out, b2);
}

// round 3
// speedup vs baseline: 1.5065x; 1.2480x over previous
#include <cuda_runtime.h>

#define N_NODES 100000
#define N_EDGES 1600000
#define TOT_E   (N_EDGES + N_NODES)   // edges + self loops
#define F_IN    128
#define HEADS   8
#define HID     8
#define HC      64
#define NCLS    40
#define NEG_SLOPE 0.2f
#define NB_SCAN 98                     // ceil((N_NODES+1)/1024)

// ---------------- scratch (static device globals) ---------------------------
__device__ __align__(16) float g_h1 [N_NODES * HC];
__device__ __align__(16) float g_o1 [N_NODES * HC];
__device__ float g_as1[N_NODES * HEADS];
__device__ float g_ad1[N_NODES * HEADS];
__device__ __align__(16) float g_h2 [N_NODES * NCLS];
__device__ float g_as2[N_NODES];
__device__ float g_ad2[N_NODES];
__device__ __align__(8) int2 g_edge[TOT_E];
__device__ int  g_csr_src[TOT_E];
__device__ int  g_deg[N_NODES + 1];
__device__ int  g_off[N_NODES + 1];
__device__ int  g_pos[N_NODES];
__device__ int  g_bsum[NB_SCAN];
__device__ int  g_is64;

__device__ __forceinline__ float lrelu(float x) { return x > 0.f ? x : NEG_SLOPE * x; }

// ---------------- dtype probe ------------------------------------------------
__global__ void probe_dtype(const long long* __restrict__ ei) {
    if (threadIdx.x == 0) {
        int ok = 1;
        for (int k = 0; k < 256; k++) {
            long long v = ei[k];
            if (v < 0 || v >= (long long)N_NODES) { ok = 0; break; }
        }
        g_is64 = ok;
    }
}

__global__ void zero_deg() {
    unsigned i = blockIdx.x * 256u + threadIdx.x;
    if (i <= N_NODES) g_deg[i] = 0;
}

// decode edges (+ self loops) and histogram destinations
__global__ void decode_hist(const void* __restrict__ ei) {
    unsigned e = blockIdx.x * 256u + threadIdx.x;
    if (e >= (unsigned)TOT_E) return;
    int s, d;
    if (e < (unsigned)N_EDGES) {
        if (g_is64) {
            const long long* p = (const long long*)ei;
            s = (int)p[e]; d = (int)p[N_EDGES + e];
        } else {
            const int* p = (const int*)ei;
            s = p[e]; d = p[N_EDGES + e];
        }
    } else {
        s = d = (int)(e - (unsigned)N_EDGES);
    }
    g_edge[e] = make_int2(s, d);
    atomicAdd(&g_deg[d], 1);
}

// block-local exclusive scan (1024/block) + block sums
__global__ void __launch_bounds__(1024) scan_blocks() {
    __shared__ int sh[1024];
    int t = threadIdx.x;
    unsigned i = blockIdx.x * 1024u + t;
    int v = (i <= N_NODES) ? g_deg[i] : 0;
    sh[t] = v; __syncthreads();
#pragma unroll
    for (int off = 1; off < 1024; off <<= 1) {
        int add = (t >= off) ? sh[t - off] : 0;
        __syncthreads();
        sh[t] += add;
        __syncthreads();
    }
    if (i <= N_NODES) g_off[i] = sh[t] - v;
    if (t == 1023) g_bsum[blockIdx.x] = sh[t];
}

__global__ void __launch_bounds__(128) scan_bsum() {
    __shared__ int sh[128];
    int t = threadIdx.x;
    int v = (t < NB_SCAN) ? g_bsum[t] : 0;
    sh[t] = v; __syncthreads();
#pragma unroll
    for (int off = 1; off < 128; off <<= 1) {
        int add = (t >= off) ? sh[t - off] : 0;
        __syncthreads();
        sh[t] += add;
        __syncthreads();
    }
    if (t < NB_SCAN) g_bsum[t] = sh[t] - v;   // exclusive
}

__global__ void fixup_offsets() {
    unsigned i = blockIdx.x * 256u + threadIdx.x;
    if (i > N_NODES) return;
    int o = g_off[i] + g_bsum[i >> 10];
    g_off[i] = o;
    if (i < N_NODES) g_pos[i] = o;
}

__global__ void scatter_csr() {
    unsigned e = blockIdx.x * 256u + threadIdx.x;
    if (e >= (unsigned)TOT_E) return;
    int2 ed = g_edge[e];
    int p = atomicAdd(&g_pos[ed.y], 1);
    g_csr_src[p] = ed.x;
}

// ---------------- layer 1 GEMM + attention logits ---------------------------
__global__ void __launch_bounds__(256) gemm1(const float* __restrict__ x,
                                             const float* __restrict__ W,
                                             const float* __restrict__ asrc,
                                             const float* __restrict__ adst) {
    __shared__ float  Ws[F_IN * HC];
    __shared__ float4 xs[8][F_IN];
    __shared__ float  as_s[HC], ad_s[HC];

    int tid = threadIdx.x;
    for (int i = tid; i < F_IN * HC; i += 256) Ws[i] = W[i];
    if (tid < HC) { as_s[tid] = asrc[tid]; ad_s[tid] = adst[tid]; }

    int warp = tid >> 5, lane = tid & 31;
    int n0 = blockIdx.x * 32 + warp * 4;

    for (int k = lane; k < F_IN; k += 32) {
        float4 v;
        v.x = x[(n0 + 0) * F_IN + k];
        v.y = x[(n0 + 1) * F_IN + k];
        v.z = x[(n0 + 2) * F_IN + k];
        v.w = x[(n0 + 3) * F_IN + k];
        xs[warp][k] = v;
    }
    __syncthreads();

    float a00 = 0, a01 = 0, a10 = 0, a11 = 0, a20 = 0, a21 = 0, a30 = 0, a31 = 0;
    const float2* W2p = (const float2*)Ws;
#pragma unroll 8
    for (int k = 0; k < F_IN; k++) {
        float4 xv = xs[warp][k];
        float2 wv = W2p[k * 32 + lane];
        a00 += xv.x * wv.x; a01 += xv.x * wv.y;
        a10 += xv.y * wv.x; a11 += xv.y * wv.y;
        a20 += xv.z * wv.x; a21 += xv.z * wv.y;
        a30 += xv.w * wv.x; a31 += xv.w * wv.y;
    }

    int j0 = lane * 2;
    float asx = as_s[j0], asy = as_s[j0 + 1];
    float adx = ad_s[j0], ady = ad_s[j0 + 1];

#define EMIT(E, A0, A1)                                                          \
    {                                                                            \
        int n = n0 + (E);                                                        \
        g_h1[n * HC + j0] = (A0); g_h1[n * HC + j0 + 1] = (A1);                  \
        float ps = (A0) * asx + (A1) * asy;                                      \
        float pd = (A0) * adx + (A1) * ady;                                      \
        ps += __shfl_xor_sync(0xffffffffu, ps, 1);                               \
        ps += __shfl_xor_sync(0xffffffffu, ps, 2);                               \
        pd += __shfl_xor_sync(0xffffffffu, pd, 1);                               \
        pd += __shfl_xor_sync(0xffffffffu, pd, 2);                               \
        if ((lane & 3) == 0) {                                                   \
            g_as1[n * HEADS + (lane >> 2)] = ps;                                 \
            g_ad1[n * HEADS + (lane >> 2)] = pd;                                 \
        }                                                                        \
    }
    EMIT(0, a00, a01) EMIT(1, a10, a11) EMIT(2, a20, a21) EMIT(3, a30, a31)
#undef EMIT
}

// ---------------- layer 1 CSR aggregation (warp per node, fused finalize) ---
__global__ void __launch_bounds__(256) edge_csr1(const float* __restrict__ b1) {
    int warp = (blockIdx.x * 256 + threadIdx.x) >> 5;
    int l = threadIdx.x & 31;
    if (warp >= N_NODES) return;
    int n = warp;
    int k = g_off[n], end = g_off[n + 1];

    float ad = (l < 8) ? g_ad1[n * 8 + l] : 0.f;
    float den = 0.f;
    float2 acc = make_float2(0.f, 0.f);

    while (k < end) {
        int cnt = min(32, end - k);
        int sv = (l < cnt) ? g_csr_src[k + l] : 0;
        for (int j = 0; j < cnt; j++) {
            int s = __shfl_sync(0xffffffffu, sv, j);
            float exl = 0.f;
            if (l < 8) {
                exl = __expf(lrelu(g_as1[s * 8 + l] + ad));
                den += exl;
            }
            float ex = __shfl_sync(0xffffffffu, exl, l >> 2);
            float2 hv = ((const float2*)g_h1)[s * 32 + l];
            acc.x += ex * hv.x;
            acc.y += ex * hv.y;
        }
        k += cnt;
    }

    float denl = __shfl_sync(0xffffffffu, den, l >> 2);
    float2 bias = ((const float2*)b1)[l];
    float inv = 1.f / (denl + 1e-16f);
    float2 r;
    r.x = fmaxf(acc.x * inv + bias.x, 0.f);   // ReLU fused
    r.y = fmaxf(acc.y * inv + bias.y, 0.f);
    ((float2*)g_o1)[n * 32 + l] = r;
}

// ---------------- layer 2 GEMM + attention logits ---------------------------
__global__ void __launch_bounds__(256) gemm2(const float* __restrict__ W2,
                                             const float* __restrict__ as2,
                                             const float* __restrict__ ad2) {
    __shared__ float Ws[HC * NCLS];
    __shared__ float hs[8][HC];
    __shared__ float a2s[NCLS], a2d[NCLS];

    int tid = threadIdx.x;
    for (int i = tid; i < HC * NCLS; i += 256) Ws[i] = W2[i];
    if (tid < NCLS) { a2s[tid] = as2[tid]; a2d[tid] = ad2[tid]; }

    int warp = tid >> 5, lane = tid & 31;
    int n = blockIdx.x * 8 + warp;
    hs[warp][lane]      = g_o1[n * HC + lane];
    hs[warp][lane + 32] = g_o1[n * HC + lane + 32];
    __syncthreads();

    float acc0 = 0.f, acc1 = 0.f;
    int l8 = 32 + (lane & 7);
#pragma unroll 8
    for (int k = 0; k < HC; k++) {
        float hv = hs[warp][k];
        acc0 += hv * Ws[k * NCLS + lane];
        acc1 += hv * Ws[k * NCLS + l8];
    }

    g_h2[n * NCLS + lane] = acc0;
    if (lane < 8) g_h2[n * NCLS + 32 + lane] = acc1;

    float ps = acc0 * a2s[lane] + (lane < 8 ? acc1 * a2s[32 + lane] : 0.f);
    float pd = acc0 * a2d[lane] + (lane < 8 ? acc1 * a2d[32 + lane] : 0.f);
#pragma unroll
    for (int o = 16; o; o >>= 1) {
        ps += __shfl_xor_sync(0xffffffffu, ps, o);
        pd += __shfl_xor_sync(0xffffffffu, pd, o);
    }
    if (lane == 0) { g_as2[n] = ps; g_ad2[n] = pd; }
}

// ---------------- layer 2 CSR aggregation (warp per node, fused finalize) ---
__global__ void __launch_bounds__(256) edge_csr2(float* __restrict__ out,
                                                 const float* __restrict__ b2) {
    int warp = (blockIdx.x * 256 + threadIdx.x) >> 5;
    int l = threadIdx.x & 31;
    if (warp >= N_NODES) return;
    int n = warp;
    int k = g_off[n], end = g_off[n + 1];

    float ad = g_ad2[n];
    float den = 0.f;
    float2 acc = make_float2(0.f, 0.f);

    while (k < end) {
        int cnt = min(32, end - k);
        int sv = (l < cnt) ? g_csr_src[k + l] : 0;
        for (int j = 0; j < cnt; j++) {
            int s = __shfl_sync(0xffffffffu, sv, j);
            float ex = __expf(lrelu(g_as2[s] + ad));   // broadcast load, one MUFU
            den += ex;
            if (l < 20) {
                float2 hv = ((const float2*)g_h2)[s * 20 + l];
                acc.x += ex * hv.x;
                acc.y += ex * hv.y;
            }
        }
        k += cnt;
    }

    if (l < 20) {
        float2 bias = ((const float2*)b2)[l];
        float inv = 1.f / (den + 1e-16f);
        float2 r;
        r.x = acc.x * inv + bias.x;
        r.y = acc.y * inv + bias.y;
        ((float2*)out)[n * 20 + l] = r;
    }
}

// ---------------- launch -----------------------------------------------------
extern "C" void kernel_launch(void* const* d_in, const int* in_sizes, int n_in,
                              void* d_out, int out_size) {
    const float* x   = (const float*)d_in[0];
    const void*  ei  = d_in[1];
    const float* W1  = (const float*)d_in[2];
    const float* as1 = (const float*)d_in[3];
    const float* ad1 = (const float*)d_in[4];
    const float* b1  = (const float*)d_in[5];
    const float* W2  = (const float*)d_in[6];
    const float* as2 = (const float*)d_in[7];
    const float* ad2 = (const float*)d_in[8];
    const float* b2  = (const float*)d_in[9];
    float*       out = (float*)d_out;

    probe_dtype<<<1, 32>>>((const long long*)ei);

    // ---- CSR build ----
    zero_deg<<<(N_NODES + 256) / 256, 256>>>();
    decode_hist<<<((unsigned)TOT_E + 255) / 256, 256>>>(ei);
    scan_blocks<<<NB_SCAN, 1024>>>();
    scan_bsum<<<1, 128>>>();
    fixup_offsets<<<(N_NODES + 256) / 256, 256>>>();
    scatter_csr<<<((unsigned)TOT_E + 255) / 256, 256>>>();

    // ---- layer 1 ----
    gemm1<<<N_NODES / 32, 256>>>(x, W1, as1, ad1);
    edge_csr1<<<(N_NODES * 32 + 255) / 256, 256>>>(b1);

    // ---- layer 2 ----
    gemm2<<<N_NODES / 8, 256>>>(W2, as2, ad2);
    edge_csr2<<<(N_NODES * 32 + 255) / 256, 256>>>(out, b2);
}

// round 4
// speedup vs baseline: 1.5354x; 1.0192x over previous
#include <cuda_runtime.h>

#define N_NODES 100000
#define N_EDGES 1600000
#define TOT_E   (N_EDGES + N_NODES)   // edges + self loops
#define F_IN    128
#define HEADS   8
#define HID     8
#define HC      64
#define NCLS    40
#define NEG_SLOPE 0.2f
#define NB_SCAN 98                     // ceil((N_NODES+1)/1024)

// ---------------- scratch (static device globals) ---------------------------
__device__ __align__(16) float g_h1 [N_NODES * HC];
__device__ __align__(16) float g_o1 [N_NODES * HC];
__device__ float g_as1[N_NODES * HEADS];
__device__ float g_ad1[N_NODES * HEADS];
__device__ __align__(16) float g_h2 [N_NODES * NCLS];
__device__ float g_as2[N_NODES];
__device__ float g_ad2[N_NODES];
__device__ int  g_csr_src[TOT_E];
__device__ int  g_deg[N_NODES + 1];
__device__ int  g_off[N_NODES + 1];
__device__ int  g_pos[N_NODES];
__device__ int  g_bsum[NB_SCAN];
__device__ int  g_is64;

__device__ __forceinline__ float lrelu(float x) { return x > 0.f ? x : NEG_SLOPE * x; }

// ---------------- dtype probe ------------------------------------------------
__global__ void probe_dtype(const long long* __restrict__ ei) {
    if (threadIdx.x == 0) {
        int ok = 1;
        for (int k = 0; k < 256; k++) {
            long long v = ei[k];
            if (v < 0 || v >= (long long)N_NODES) { ok = 0; break; }
        }
        g_is64 = ok;
    }
}

__global__ void zero_deg() {
    unsigned i = blockIdx.x * 256u + threadIdx.x;
    if (i <= N_NODES) g_deg[i] = 0;
}

// histogram destinations straight from edge_index (no intermediate edge array)
__global__ void hist_dst(const void* __restrict__ ei) {
    unsigned e = blockIdx.x * 256u + threadIdx.x;
    if (e >= (unsigned)TOT_E) return;
    int d;
    if (e < (unsigned)N_EDGES) {
        d = g_is64 ? (int)((const long long*)ei)[N_EDGES + e]
                   : ((const int*)ei)[N_EDGES + e];
    } else {
        d = (int)(e - (unsigned)N_EDGES);
    }
    atomicAdd(&g_deg[d], 1);
}

// block-local exclusive scan (1024/block) + block sums
__global__ void __launch_bounds__(1024) scan_blocks() {
    __shared__ int sh[1024];
    int t = threadIdx.x;
    unsigned i = blockIdx.x * 1024u + t;
    int v = (i <= N_NODES) ? g_deg[i] : 0;
    sh[t] = v; __syncthreads();
#pragma unroll
    for (int off = 1; off < 1024; off <<= 1) {
        int add = (t >= off) ? sh[t - off] : 0;
        __syncthreads();
        sh[t] += add;
        __syncthreads();
    }
    if (i <= N_NODES) g_off[i] = sh[t] - v;
    if (t == 1023) g_bsum[blockIdx.x] = sh[t];
}

__global__ void __launch_bounds__(128) scan_bsum() {
    __shared__ int sh[128];
    int t = threadIdx.x;
    int v = (t < NB_SCAN) ? g_bsum[t] : 0;
    sh[t] = v; __syncthreads();
#pragma unroll
    for (int off = 1; off < 128; off <<= 1) {
        int add = (t >= off) ? sh[t - off] : 0;
        __syncthreads();
        sh[t] += add;
        __syncthreads();
    }
    if (t < NB_SCAN) g_bsum[t] = sh[t] - v;   // exclusive
}

__global__ void fixup_offsets() {
    unsigned i = blockIdx.x * 256u + threadIdx.x;
    if (i > N_NODES) return;
    int o = g_off[i] + g_bsum[i >> 10];
    g_off[i] = o;
    if (i < N_NODES) g_pos[i] = o;
}

__global__ void scatter_csr(const void* __restrict__ ei) {
    unsigned e = blockIdx.x * 256u + threadIdx.x;
    if (e >= (unsigned)TOT_E) return;
    int s, d;
    if (e < (unsigned)N_EDGES) {
        if (g_is64) {
            const long long* p = (const long long*)ei;
            s = (int)p[e]; d = (int)p[N_EDGES + e];
        } else {
            const int* p = (const int*)ei;
            s = p[e]; d = p[N_EDGES + e];
        }
    } else {
        s = d = (int)(e - (unsigned)N_EDGES);
    }
    int p = atomicAdd(&g_pos[d], 1);
    g_csr_src[p] = s;
}

// ---------------- layer 1 GEMM + attention logits ---------------------------
__global__ void __launch_bounds__(256) gemm1(const float* __restrict__ x,
                                             const float* __restrict__ W,
                                             const float* __restrict__ asrc,
                                             const float* __restrict__ adst) {
    __shared__ float  Ws[F_IN * HC];
    __shared__ float4 xs[8][F_IN];
    __shared__ float  as_s[HC], ad_s[HC];

    int tid = threadIdx.x;
    for (int i = tid; i < F_IN * HC; i += 256) Ws[i] = W[i];
    if (tid < HC) { as_s[tid] = asrc[tid]; ad_s[tid] = adst[tid]; }

    int warp = tid >> 5, lane = tid & 31;
    int n0 = blockIdx.x * 32 + warp * 4;

    for (int k = lane; k < F_IN; k += 32) {
        float4 v;
        v.x = x[(n0 + 0) * F_IN + k];
        v.y = x[(n0 + 1) * F_IN + k];
        v.z = x[(n0 + 2) * F_IN + k];
        v.w = x[(n0 + 3) * F_IN + k];
        xs[warp][k] = v;
    }
    __syncthreads();

    float a00 = 0, a01 = 0, a10 = 0, a11 = 0, a20 = 0, a21 = 0, a30 = 0, a31 = 0;
    const float2* W2p = (const float2*)Ws;
#pragma unroll 8
    for (int k = 0; k < F_IN; k++) {
        float4 xv = xs[warp][k];
        float2 wv = W2p[k * 32 + lane];
        a00 += xv.x * wv.x; a01 += xv.x * wv.y;
        a10 += xv.y * wv.x; a11 += xv.y * wv.y;
        a20 += xv.z * wv.x; a21 += xv.z * wv.y;
        a30 += xv.w * wv.x; a31 += xv.w * wv.y;
    }

    int j0 = lane * 2;
    float asx = as_s[j0], asy = as_s[j0 + 1];
    float adx = ad_s[j0], ady = ad_s[j0 + 1];

#define EMIT(E, A0, A1)                                                          \
    {                                                                            \
        int n = n0 + (E);                                                        \
        g_h1[n * HC + j0] = (A0); g_h1[n * HC + j0 + 1] = (A1);                  \
        float ps = (A0) * asx + (A1) * asy;                                      \
        float pd = (A0) * adx + (A1) * ady;                                      \
        ps += __shfl_xor_sync(0xffffffffu, ps, 1);                               \
        ps += __shfl_xor_sync(0xffffffffu, ps, 2);                               \
        pd += __shfl_xor_sync(0xffffffffu, pd, 1);                               \
        pd += __shfl_xor_sync(0xffffffffu, pd, 2);                               \
        if ((lane & 3) == 0) {                                                   \
            g_as1[n * HEADS + (lane >> 2)] = ps;                                 \
            g_ad1[n * HEADS + (lane >> 2)] = pd;                                 \
        }                                                                        \
    }
    EMIT(0, a00, a01) EMIT(1, a10, a11) EMIT(2, a20, a21) EMIT(3, a30, a31)
#undef EMIT
}

// ---------------- layer 1 CSR aggregation ------------------------------------
// warp per node; lane l owns head hl=(l&7), channels c0=(hl*8)+(l>>3)*2, c0+1.
// Every lane computes its own exp (one warp-wide MUFU) -> no shuffles except
// the src broadcast. Inner loop unrolled x4 for MLP.
__global__ void __launch_bounds__(256) edge_csr1(const float* __restrict__ b1) {
    int warp = (blockIdx.x * 256 + threadIdx.x) >> 5;
    int l = threadIdx.x & 31;
    if (warp >= N_NODES) return;
    int n = warp;
    int hl = l & 7;
    int c0 = hl * 8 + (l >> 3) * 2;

    float ad = g_ad1[n * 8 + hl];
    float den = 0.f;
    float2 acc = make_float2(0.f, 0.f);

    int k = g_off[n], end = g_off[n + 1];
    while (k < end) {
        int cnt = min(32, end - k);
        int sv = (l < cnt) ? g_csr_src[k + l] : 0;
        int j = 0;
        for (; j + 4 <= cnt; j += 4) {
            int s0 = __shfl_sync(0xffffffffu, sv, j);
            int s1 = __shfl_sync(0xffffffffu, sv, j + 1);
            int s2 = __shfl_sync(0xffffffffu, sv, j + 2);
            int s3 = __shfl_sync(0xffffffffu, sv, j + 3);
            float t0 = g_as1[s0 * 8 + hl];
            float t1 = g_as1[s1 * 8 + hl];
            float t2 = g_as1[s2 * 8 + hl];
            float t3 = g_as1[s3 * 8 + hl];
            float2 h0 = *(const float2*)(g_h1 + s0 * HC + c0);
            float2 h1 = *(const float2*)(g_h1 + s1 * HC + c0);
            float2 h2 = *(const float2*)(g_h1 + s2 * HC + c0);
            float2 h3 = *(const float2*)(g_h1 + s3 * HC + c0);
            float e0 = __expf(lrelu(t0 + ad));
            float e1 = __expf(lrelu(t1 + ad));
            float e2 = __expf(lrelu(t2 + ad));
            float e3 = __expf(lrelu(t3 + ad));
            den += (e0 + e1) + (e2 + e3);
            acc.x += e0 * h0.x + e1 * h1.x + e2 * h2.x + e3 * h3.x;
            acc.y += e0 * h0.y + e1 * h1.y + e2 * h2.y + e3 * h3.y;
        }
        for (; j < cnt; j++) {
            int s = __shfl_sync(0xffffffffu, sv, j);
            float e = __expf(lrelu(g_as1[s * 8 + hl] + ad));
            float2 hv = *(const float2*)(g_h1 + s * HC + c0);
            den += e;
            acc.x += e * hv.x;
            acc.y += e * hv.y;
        }
        k += cnt;
    }

    float2 bias = *(const float2*)(b1 + c0);
    float inv = 1.f / (den + 1e-16f);
    float2 r;
    r.x = fmaxf(acc.x * inv + bias.x, 0.f);   // ReLU fused
    r.y = fmaxf(acc.y * inv + bias.y, 0.f);
    *(float2*)(g_o1 + n * HC + c0) = r;
}

// ---------------- layer 2 GEMM + attention logits ---------------------------
__global__ void __launch_bounds__(256) gemm2(const float* __restrict__ W2,
                                             const float* __restrict__ as2,
                                             const float* __restrict__ ad2) {
    __shared__ float Ws[HC * NCLS];
    __shared__ float hs[8][HC];
    __shared__ float a2s[NCLS], a2d[NCLS];

    int tid = threadIdx.x;
    for (int i = tid; i < HC * NCLS; i += 256) Ws[i] = W2[i];
    if (tid < NCLS) { a2s[tid] = as2[tid]; a2d[tid] = ad2[tid]; }

    int warp = tid >> 5, lane = tid & 31;
    int n = blockIdx.x * 8 + warp;
    hs[warp][lane]      = g_o1[n * HC + lane];
    hs[warp][lane + 32] = g_o1[n * HC + lane + 32];
    __syncthreads();

    float acc0 = 0.f, acc1 = 0.f;
    int l8 = 32 + (lane & 7);
#pragma unroll 8
    for (int k = 0; k < HC; k++) {
        float hv = hs[warp][k];
        acc0 += hv * Ws[k * NCLS + lane];
        acc1 += hv * Ws[k * NCLS + l8];
    }

    g_h2[n * NCLS + lane] = acc0;
    if (lane < 8) g_h2[n * NCLS + 32 + lane] = acc1;

    float ps = acc0 * a2s[lane] + (lane < 8 ? acc1 * a2s[32 + lane] : 0.f);
    float pd = acc0 * a2d[lane] + (lane < 8 ? acc1 * a2d[32 + lane] : 0.f);
#pragma unroll
    for (int o = 16; o; o >>= 1) {
        ps += __shfl_xor_sync(0xffffffffu, ps, o);
        pd += __shfl_xor_sync(0xffffffffu, pd, o);
    }
    if (lane == 0) { g_as2[n] = ps; g_ad2[n] = pd; }
}

// ---------------- layer 2 CSR aggregation ------------------------------------
__global__ void __launch_bounds__(256) edge_csr2(float* __restrict__ out,
                                                 const float* __restrict__ b2) {
    int warp = (blockIdx.x * 256 + threadIdx.x) >> 5;
    int l = threadIdx.x & 31;
    if (warp >= N_NODES) return;
    int n = warp;
    bool act = l < 20;

    float ad = g_ad2[n];
    float den = 0.f;
    float2 acc = make_float2(0.f, 0.f);

    int k = g_off[n], end = g_off[n + 1];
    while (k < end) {
        int cnt = min(32, end - k);
        int sv = (l < cnt) ? g_csr_src[k + l] : 0;
        int j = 0;
        for (; j + 4 <= cnt; j += 4) {
            int s0 = __shfl_sync(0xffffffffu, sv, j);
            int s1 = __shfl_sync(0xffffffffu, sv, j + 1);
            int s2 = __shfl_sync(0xffffffffu, sv, j + 2);
            int s3 = __shfl_sync(0xffffffffu, sv, j + 3);
            float t0 = g_as2[s0];
            float t1 = g_as2[s1];
            float t2 = g_as2[s2];
            float t3 = g_as2[s3];
            float2 h0, h1, h2, h3;
            if (act) {
                h0 = *(const float2*)(g_h2 + s0 * NCLS + l * 2);
                h1 = *(const float2*)(g_h2 + s1 * NCLS + l * 2);
                h2 = *(const float2*)(g_h2 + s2 * NCLS + l * 2);
                h3 = *(const float2*)(g_h2 + s3 * NCLS + l * 2);
            }
            float e0 = __expf(lrelu(t0 + ad));
            float e1 = __expf(lrelu(t1 + ad));
            float e2 = __expf(lrelu(t2 + ad));
            float e3 = __expf(lrelu(t3 + ad));
            den += (e0 + e1) + (e2 + e3);
            if (act) {
                acc.x += e0 * h0.x + e1 * h1.x + e2 * h2.x + e3 * h3.x;
                acc.y += e0 * h0.y + e1 * h1.y + e2 * h2.y + e3 * h3.y;
            }
        }
        for (; j < cnt; j++) {
            int s = __shfl_sync(0xffffffffu, sv, j);
            float e = __expf(lrelu(g_as2[s] + ad));
            den += e;
            if (act) {
                float2 hv = *(const float2*)(g_h2 + s * NCLS + l * 2);
                acc.x += e * hv.x;
                acc.y += e * hv.y;
            }
        }
        k += cnt;
    }

    if (act) {
        float2 bias = *(const float2*)(b2 + l * 2);
        float inv = 1.f / (den + 1e-16f);
        float2 r;
        r.x = acc.x * inv + bias.x;
        r.y = acc.y * inv + bias.y;
        *(float2*)(out + n * NCLS + l * 2) = r;
    }
}

// ---------------- launch -----------------------------------------------------
extern "C" void kernel_launch(void* const* d_in, const int* in_sizes, int n_in,
                              void* d_out, int out_size) {
    const float* x   = (const float*)d_in[0];
    const void*  ei  = d_in[1];
    const float* W1  = (const float*)d_in[2];
    const float* as1 = (const float*)d_in[3];
    const float* ad1 = (const float*)d_in[4];
    const float* b1  = (const float*)d_in[5];
    const float* W2  = (const float*)d_in[6];
    const float* as2 = (const float*)d_in[7];
    const float* ad2 = (const float*)d_in[8];
    const float* b2  = (const float*)d_in[9];
    float*       out = (float*)d_out;

    probe_dtype<<<1, 32>>>((const long long*)ei);

    // ---- CSR build ----
    zero_deg<<<(N_NODES + 256) / 256, 256>>>();
    hist_dst<<<((unsigned)TOT_E + 255) / 256, 256>>>(ei);
    scan_blocks<<<NB_SCAN, 1024>>>();
    scan_bsum<<<1, 128>>>();
    fixup_offsets<<<(N_NODES + 256) / 256, 256>>>();
    scatter_csr<<<((unsigned)TOT_E + 255) / 256, 256>>>(ei);

    // ---- layer 1 ----
    gemm1<<<N_NODES / 32, 256>>>(x, W1, as1, ad1);
    edge_csr1<<<(N_NODES * 32 + 255) / 256, 256>>>(b1);

    // ---- layer 2 ----
    gemm2<<<N_NODES / 8, 256>>>(W2, as2, ad2);
    edge_csr2<<<(N_NODES * 32 + 255) / 256, 256>>>(out, b2);
}

// round 5
// speedup vs baseline: 1.6207x; 1.0556x over previous
#include <cuda_runtime.h>
#include <cuda_fp16.h>

#define N_NODES 100000
#define N_EDGES 1600000
#define TOT_E   (N_EDGES + N_NODES)   // edges + self loops
#define F_IN    128
#define HEADS   8
#define HID     8
#define HC      64
#define NCLS    40
#define NEG_SLOPE 0.2f
#define NB_SCAN 98                     // ceil((N_NODES+1)/1024)

// ---------------- scratch (static device globals) ---------------------------
__device__ __align__(16) __half2 g_h1h[N_NODES * 32];   // layer1 features, fp16 pairs
__device__ __align__(16) float   g_o1 [N_NODES * HC];   // layer1 activated out (fp32)
__device__ float g_as1[N_NODES * HEADS];
__device__ float g_ad1[N_NODES * HEADS];
__device__ __align__(16) __half2 g_h2h[N_NODES * 20];   // layer2 features, fp16 pairs
__device__ float g_as2[N_NODES];
__device__ float g_ad2[N_NODES];
__device__ int  g_csr_src[TOT_E];
__device__ int  g_deg[N_NODES + 1];
__device__ int  g_off[N_NODES + 1];
__device__ int  g_pos[N_NODES];
__device__ int  g_bsum[NB_SCAN];
__device__ int  g_is64;

__device__ __forceinline__ float lrelu(float x) { return x > 0.f ? x : NEG_SLOPE * x; }

// ---------------- dtype probe (one warp, ballot) -----------------------------
__global__ void probe_dtype(const long long* __restrict__ ei) {
    int l = threadIdx.x;
    int bad = 0;
#pragma unroll
    for (int k = 0; k < 8; k++) {
        long long v = ei[l * 8 + k];
        if (v < 0 || v >= (long long)N_NODES) bad = 1;
    }
    unsigned m = __ballot_sync(0xffffffffu, bad);
    if (l == 0) g_is64 = (m == 0u);
}

__global__ void zero_deg() {
    unsigned i = blockIdx.x * 256u + threadIdx.x;
    if (i <= N_NODES) g_deg[i] = 0;
}

// histogram destinations straight from edge_index
__global__ void hist_dst(const void* __restrict__ ei) {
    unsigned e = blockIdx.x * 256u + threadIdx.x;
    if (e >= (unsigned)TOT_E) return;
    int d;
    if (e < (unsigned)N_EDGES) {
        d = g_is64 ? (int)((const long long*)ei)[N_EDGES + e]
                   : ((const int*)ei)[N_EDGES + e];
    } else {
        d = (int)(e - (unsigned)N_EDGES);
    }
    atomicAdd(&g_deg[d], 1);
}

// block-local exclusive scan (1024/block) + block sums
__global__ void __launch_bounds__(1024) scan_blocks() {
    __shared__ int sh[1024];
    int t = threadIdx.x;
    unsigned i = blockIdx.x * 1024u + t;
    int v = (i <= N_NODES) ? g_deg[i] : 0;
    sh[t] = v; __syncthreads();
#pragma unroll
    for (int off = 1; off < 1024; off <<= 1) {
        int add = (t >= off) ? sh[t - off] : 0;
        __syncthreads();
        sh[t] += add;
        __syncthreads();
    }
    if (i <= N_NODES) g_off[i] = sh[t] - v;
    if (t == 1023) g_bsum[blockIdx.x] = sh[t];
}

__global__ void __launch_bounds__(128) scan_bsum() {
    __shared__ int sh[128];
    int t = threadIdx.x;
    int v = (t < NB_SCAN) ? g_bsum[t] : 0;
    sh[t] = v; __syncthreads();
#pragma unroll
    for (int off = 1; off < 128; off <<= 1) {
        int add = (t >= off) ? sh[t - off] : 0;
        __syncthreads();
        sh[t] += add;
        __syncthreads();
    }
    if (t < NB_SCAN) g_bsum[t] = sh[t] - v;   // exclusive
}

__global__ void fixup_offsets() {
    unsigned i = blockIdx.x * 256u + threadIdx.x;
    if (i > N_NODES) return;
    int o = g_off[i] + g_bsum[i >> 10];
    g_off[i] = o;
    if (i < N_NODES) g_pos[i] = o;
}

__global__ void scatter_csr(const void* __restrict__ ei) {
    unsigned e = blockIdx.x * 256u + threadIdx.x;
    if (e >= (unsigned)TOT_E) return;
    int s, d;
    if (e < (unsigned)N_EDGES) {
        if (g_is64) {
            const long long* p = (const long long*)ei;
            s = (int)p[e]; d = (int)p[N_EDGES + e];
        } else {
            const int* p = (const int*)ei;
            s = p[e]; d = p[N_EDGES + e];
        }
    } else {
        s = d = (int)(e - (unsigned)N_EDGES);
    }
    int p = atomicAdd(&g_pos[d], 1);
    g_csr_src[p] = s;
}

// ---------------- layer 1 GEMM + attention logits ---------------------------
__global__ void __launch_bounds__(256) gemm1(const float* __restrict__ x,
                                             const float* __restrict__ W,
                                             const float* __restrict__ asrc,
                                             const float* __restrict__ adst) {
    __shared__ float  Ws[F_IN * HC];
    __shared__ float4 xs[8][F_IN];
    __shared__ float  as_s[HC], ad_s[HC];

    int tid = threadIdx.x;
    for (int i = tid; i < F_IN * HC; i += 256) Ws[i] = W[i];
    if (tid < HC) { as_s[tid] = asrc[tid]; ad_s[tid] = adst[tid]; }

    int warp = tid >> 5, lane = tid & 31;
    int n0 = blockIdx.x * 32 + warp * 4;

    for (int k = lane; k < F_IN; k += 32) {
        float4 v;
        v.x = x[(n0 + 0) * F_IN + k];
        v.y = x[(n0 + 1) * F_IN + k];
        v.z = x[(n0 + 2) * F_IN + k];
        v.w = x[(n0 + 3) * F_IN + k];
        xs[warp][k] = v;
    }
    __syncthreads();

    float a00 = 0, a01 = 0, a10 = 0, a11 = 0, a20 = 0, a21 = 0, a30 = 0, a31 = 0;
    const float2* W2p = (const float2*)Ws;
#pragma unroll 8
    for (int k = 0; k < F_IN; k++) {
        float4 xv = xs[warp][k];
        float2 wv = W2p[k * 32 + lane];
        a00 += xv.x * wv.x; a01 += xv.x * wv.y;
        a10 += xv.y * wv.x; a11 += xv.y * wv.y;
        a20 += xv.z * wv.x; a21 += xv.z * wv.y;
        a30 += xv.w * wv.x; a31 += xv.w * wv.y;
    }

    int j0 = lane * 2;
    float asx = as_s[j0], asy = as_s[j0 + 1];
    float adx = ad_s[j0], ady = ad_s[j0 + 1];

#define EMIT(E, A0, A1)                                                          \
    {                                                                            \
        int n = n0 + (E);                                                        \
        g_h1h[n * 32 + lane] = __floats2half2_rn((A0), (A1));                    \
        float ps = (A0) * asx + (A1) * asy;                                      \
        float pd = (A0) * adx + (A1) * ady;                                      \
        ps += __shfl_xor_sync(0xffffffffu, ps, 1);                               \
        ps += __shfl_xor_sync(0xffffffffu, ps, 2);                               \
        pd += __shfl_xor_sync(0xffffffffu, pd, 1);                               \
        pd += __shfl_xor_sync(0xffffffffu, pd, 2);                               \
        if ((lane & 3) == 0) {                                                   \
            g_as1[n * HEADS + (lane >> 2)] = ps;                                 \
            g_ad1[n * HEADS + (lane >> 2)] = pd;                                 \
        }                                                                        \
    }
    EMIT(0, a00, a01) EMIT(1, a10, a11) EMIT(2, a20, a21) EMIT(3, a30, a31)
#undef EMIT
}

// ---------------- layer 1 CSR aggregation ------------------------------------
// warp per node; lane l owns head hl=(l&7), half2 index hidx=hl*4+(l>>3)
// (channels c0=hl*8+(l>>3)*2, c0+1). One 128B line per edge.
__global__ void __launch_bounds__(256) edge_csr1(const float* __restrict__ b1) {
    int warp = (blockIdx.x * 256 + threadIdx.x) >> 5;
    int l = threadIdx.x & 31;
    if (warp >= N_NODES) return;
    int n = warp;
    int hl = l & 7;
    int hidx = hl * 4 + (l >> 3);
    int c0 = hl * 8 + (l >> 3) * 2;

    float ad = g_ad1[n * 8 + hl];
    float den = 0.f;
    float2 acc = make_float2(0.f, 0.f);

    int k = g_off[n], end = g_off[n + 1];
    while (k < end) {
        int cnt = min(32, end - k);
        int sv = (l < cnt) ? g_csr_src[k + l] : 0;
        int j = 0;
        for (; j + 4 <= cnt; j += 4) {
            int s0 = __shfl_sync(0xffffffffu, sv, j);
            int s1 = __shfl_sync(0xffffffffu, sv, j + 1);
            int s2 = __shfl_sync(0xffffffffu, sv, j + 2);
            int s3 = __shfl_sync(0xffffffffu, sv, j + 3);
            float t0 = g_as1[s0 * 8 + hl];
            float t1 = g_as1[s1 * 8 + hl];
            float t2 = g_as1[s2 * 8 + hl];
            float t3 = g_as1[s3 * 8 + hl];
            float2 h0 = __half22float2(g_h1h[s0 * 32 + hidx]);
            float2 h1 = __half22float2(g_h1h[s1 * 32 + hidx]);
            float2 h2 = __half22float2(g_h1h[s2 * 32 + hidx]);
            float2 h3 = __half22float2(g_h1h[s3 * 32 + hidx]);
            float e0 = __expf(lrelu(t0 + ad));
            float e1 = __expf(lrelu(t1 + ad));
            float e2 = __expf(lrelu(t2 + ad));
            float e3 = __expf(lrelu(t3 + ad));
            den += (e0 + e1) + (e2 + e3);
            acc.x += e0 * h0.x + e1 * h1.x + e2 * h2.x + e3 * h3.x;
            acc.y += e0 * h0.y + e1 * h1.y + e2 * h2.y + e3 * h3.y;
        }
        for (; j < cnt; j++) {
            int s = __shfl_sync(0xffffffffu, sv, j);
            float e = __expf(lrelu(g_as1[s * 8 + hl] + ad));
            float2 hv = __half22float2(g_h1h[s * 32 + hidx]);
            den += e;
            acc.x += e * hv.x;
            acc.y += e * hv.y;
        }
        k += cnt;
    }

    float2 bias = *(const float2*)(b1 + c0);
    float inv = 1.f / (den + 1e-16f);
    float2 r;
    r.x = fmaxf(acc.x * inv + bias.x, 0.f);   // ReLU fused
    r.y = fmaxf(acc.y * inv + bias.y, 0.f);
    *(float2*)(g_o1 + n * HC + c0) = r;
}

// ---------------- layer 2 GEMM + attention logits ---------------------------
__global__ void __launch_bounds__(256) gemm2(const float* __restrict__ W2,
                                             const float* __restrict__ as2,
                                             const float* __restrict__ ad2) {
    __shared__ float Ws[HC * NCLS];
    __shared__ float hs[8][HC];
    __shared__ float a2s[NCLS], a2d[NCLS];

    int tid = threadIdx.x;
    for (int i = tid; i < HC * NCLS; i += 256) Ws[i] = W2[i];
    if (tid < NCLS) { a2s[tid] = as2[tid]; a2d[tid] = ad2[tid]; }

    int warp = tid >> 5, lane = tid & 31;
    int n = blockIdx.x * 8 + warp;
    hs[warp][lane]      = g_o1[n * HC + lane];
    hs[warp][lane + 32] = g_o1[n * HC + lane + 32];
    __syncthreads();

    float acc0 = 0.f, acc1 = 0.f;
    int l8 = 32 + (lane & 7);
#pragma unroll 8
    for (int k = 0; k < HC; k++) {
        float hv = hs[warp][k];
        acc0 += hv * Ws[k * NCLS + lane];
        acc1 += hv * Ws[k * NCLS + l8];
    }

    __half* h2p = (__half*)g_h2h;
    h2p[n * NCLS + lane] = __float2half_rn(acc0);
    if (lane < 8) h2p[n * NCLS + 32 + lane] = __float2half_rn(acc1);

    float ps = acc0 * a2s[lane] + (lane < 8 ? acc1 * a2s[32 + lane] : 0.f);
    float pd = acc0 * a2d[lane] + (lane < 8 ? acc1 * a2d[32 + lane] : 0.f);
#pragma unroll
    for (int o = 16; o; o >>= 1) {
        ps += __shfl_xor_sync(0xffffffffu, ps, o);
        pd += __shfl_xor_sync(0xffffffffu, pd, o);
    }
    if (lane == 0) { g_as2[n] = ps; g_ad2[n] = pd; }
}

// ---------------- layer 2 CSR aggregation ------------------------------------
// lane l<20 owns classes 2l, 2l+1 (one half2).
__global__ void __launch_bounds__(256) edge_csr2(float* __restrict__ out,
                                                 const float* __restrict__ b2) {
    int warp = (blockIdx.x * 256 + threadIdx.x) >> 5;
    int l = threadIdx.x & 31;
    if (warp >= N_NODES) return;
    int n = warp;
    bool act = l < 20;
    int li = act ? l : 0;

    float ad = g_ad2[n];
    float den = 0.f;
    float2 acc = make_float2(0.f, 0.f);

    int k = g_off[n], end = g_off[n + 1];
    while (k < end) {
        int cnt = min(32, end - k);
        int sv = (l < cnt) ? g_csr_src[k + l] : 0;
        int j = 0;
        for (; j + 4 <= cnt; j += 4) {
            int s0 = __shfl_sync(0xffffffffu, sv, j);
            int s1 = __shfl_sync(0xffffffffu, sv, j + 1);
            int s2 = __shfl_sync(0xffffffffu, sv, j + 2);
            int s3 = __shfl_sync(0xffffffffu, sv, j + 3);
            float t0 = g_as2[s0];
            float t1 = g_as2[s1];
            float t2 = g_as2[s2];
            float t3 = g_as2[s3];
            float2 h0 = __half22float2(g_h2h[s0 * 20 + li]);
            float2 h1 = __half22float2(g_h2h[s1 * 20 + li]);
            float2 h2 = __half22float2(g_h2h[s2 * 20 + li]);
            float2 h3 = __half22float2(g_h2h[s3 * 20 + li]);
            float e0 = __expf(lrelu(t0 + ad));
            float e1 = __expf(lrelu(t1 + ad));
            float e2 = __expf(lrelu(t2 + ad));
            float e3 = __expf(lrelu(t3 + ad));
            den += (e0 + e1) + (e2 + e3);
            acc.x += e0 * h0.x + e1 * h1.x + e2 * h2.x + e3 * h3.x;
            acc.y += e0 * h0.y + e1 * h1.y + e2 * h2.y + e3 * h3.y;
        }
        for (; j < cnt; j++) {
            int s = __shfl_sync(0xffffffffu, sv, j);
            float e = __expf(lrelu(g_as2[s] + ad));
            float2 hv = __half22float2(g_h2h[s * 20 + li]);
            den += e;
            acc.x += e * hv.x;
            acc.y += e * hv.y;
        }
        k += cnt;
    }

    if (act) {
        float2 bias = *(const float2*)(b2 + l * 2);
        float inv = 1.f / (den + 1e-16f);
        float2 r;
        r.x = acc.x * inv + bias.x;
        r.y = acc.y * inv + bias.y;
        *(float2*)(out + n * NCLS + l * 2) = r;
    }
}

// ---------------- launch -----------------------------------------------------
extern "C" void kernel_launch(void* const* d_in, const int* in_sizes, int n_in,
                              void* d_out, int out_size) {
    const float* x   = (const float*)d_in[0];
    const void*  ei  = d_in[1];
    const float* W1  = (const float*)d_in[2];
    const float* as1 = (const float*)d_in[3];
    const float* ad1 = (const float*)d_in[4];
    const float* b1  = (const float*)d_in[5];
    const float* W2  = (const float*)d_in[6];
    const float* as2 = (const float*)d_in[7];
    const float* ad2 = (const float*)d_in[8];
    const float* b2  = (const float*)d_in[9];
    float*       out = (float*)d_out;

    probe_dtype<<<1, 32>>>((const long long*)ei);

    // ---- CSR build ----
    zero_deg<<<(N_NODES + 256) / 256, 256>>>();
    hist_dst<<<((unsigned)TOT_E + 255) / 256, 256>>>(ei);
    scan_blocks<<<NB_SCAN, 1024>>>();
    scan_bsum<<<1, 128>>>();
    fixup_offsets<<<(N_NODES + 256) / 256, 256>>>();
    scatter_csr<<<((unsigned)TOT_E + 255) / 256, 256>>>(ei);

    // ---- layer 1 ----
    gemm1<<<N_NODES / 32, 256>>>(x, W1, as1, ad1);
    edge_csr1<<<(N_NODES * 32 + 255) / 256, 256>>>(b1);

    // ---- layer 2 ----
    gemm2<<<N_NODES / 8, 256>>>(W2, as2, ad2);
    edge_csr2<<<(N_NODES * 32 + 255) / 256, 256>>>(out, b2);
}

// round 6
// speedup vs baseline: 1.7300x; 1.0674x over previous
#include <cuda_runtime.h>
#include <cuda_fp16.h>

#define N_NODES 100000
#define N_EDGES 1600000
#define TOT_E   (N_EDGES + N_NODES)   // edges + self loops
#define F_IN    128
#define HEADS   8
#define HID     8
#define HC      64
#define NCLS    40
#define NEG_SLOPE 0.2f
#define NB_SCAN 98                     // ceil((N_NODES+1)/1024)

// ---------------- scratch (static device globals) ---------------------------
__device__ __align__(16) __half2 g_h1h[N_NODES * 32];   // layer1 features, fp16 pairs
__device__ float g_as1[N_NODES * HEADS];
__device__ float g_ad1[N_NODES * HEADS];
__device__ __align__(16) __half2 g_h2h[N_NODES * 20];   // layer2 features, fp16 pairs
__device__ float g_as2[N_NODES];
__device__ float g_ad2[N_NODES];
__device__ int  g_csr_src[TOT_E];
__device__ int  g_deg[N_NODES + 1];
__device__ int  g_off[N_NODES + 1];
__device__ int  g_pos[N_NODES];
__device__ int  g_bsum[NB_SCAN];
__device__ int  g_is64;

__device__ __forceinline__ float lrelu(float x) { return x > 0.f ? x : NEG_SLOPE * x; }

// ---------------- probe dtype + zero degree array ---------------------------
__global__ void probe_zero(const long long* __restrict__ ei) {
    unsigned i = blockIdx.x * 256u + threadIdx.x;
    if (i <= N_NODES) g_deg[i] = 0;
    if (blockIdx.x == 0 && threadIdx.x < 32) {
        int l = threadIdx.x;
        int bad = 0;
#pragma unroll
        for (int k = 0; k < 8; k++) {
            long long v = ei[l * 8 + k];
            if (v < 0 || v >= (long long)N_NODES) bad = 1;
        }
        unsigned m = __ballot_sync(0xffffffffu, bad);
        if (l == 0) g_is64 = (m == 0u);
    }
}

// histogram destinations straight from edge_index
__global__ void hist_dst(const void* __restrict__ ei) {
    unsigned e = blockIdx.x * 256u + threadIdx.x;
    if (e >= (unsigned)TOT_E) return;
    int d;
    if (e < (unsigned)N_EDGES) {
        d = g_is64 ? (int)((const long long*)ei)[N_EDGES + e]
                   : ((const int*)ei)[N_EDGES + e];
    } else {
        d = (int)(e - (unsigned)N_EDGES);
    }
    atomicAdd(&g_deg[d], 1);
}

// block-local exclusive scan (1024/block) + block sums
__global__ void __launch_bounds__(1024) scan_blocks() {
    __shared__ int sh[1024];
    int t = threadIdx.x;
    unsigned i = blockIdx.x * 1024u + t;
    int v = (i <= N_NODES) ? g_deg[i] : 0;
    sh[t] = v; __syncthreads();
#pragma unroll
    for (int off = 1; off < 1024; off <<= 1) {
        int add = (t >= off) ? sh[t - off] : 0;
        __syncthreads();
        sh[t] += add;
        __syncthreads();
    }
    if (i <= N_NODES) g_off[i] = sh[t] - v;
    if (t == 1023) g_bsum[blockIdx.x] = sh[t];
}

// fixup: re-scan the 98 block sums in smem, then add to offsets
__global__ void __launch_bounds__(256) fixup_offsets() {
    __shared__ int sb[128];
    int t = threadIdx.x;
    if (t < 128) sb[t] = (t < NB_SCAN) ? g_bsum[t] : 0;
    __syncthreads();
#pragma unroll
    for (int off = 1; off < 128; off <<= 1) {
        int add = (t < 128 && t >= off) ? sb[t - off] : 0;
        __syncthreads();
        if (t < 128) sb[t] += add;
        __syncthreads();
    }
    unsigned i = blockIdx.x * 256u + t;
    if (i > N_NODES) return;
    unsigned b = i >> 10;
    int pre = (b == 0) ? 0 : sb[b - 1];       // exclusive
    int o = g_off[i] + pre;
    g_off[i] = o;
    if (i < N_NODES) g_pos[i] = o;
}

__global__ void scatter_csr(const void* __restrict__ ei) {
    unsigned e = blockIdx.x * 256u + threadIdx.x;
    if (e >= (unsigned)TOT_E) return;
    int s, d;
    if (e < (unsigned)N_EDGES) {
        if (g_is64) {
            const long long* p = (const long long*)ei;
            s = (int)p[e]; d = (int)p[N_EDGES + e];
        } else {
            const int* p = (const int*)ei;
            s = p[e]; d = p[N_EDGES + e];
        }
    } else {
        s = d = (int)(e - (unsigned)N_EDGES);
    }
    int p = atomicAdd(&g_pos[d], 1);
    g_csr_src[p] = s;
}

// ---------------- layer 1 GEMM + attention logits ---------------------------
__global__ void __launch_bounds__(256) gemm1(const float* __restrict__ x,
                                             const float* __restrict__ W,
                                             const float* __restrict__ asrc,
                                             const float* __restrict__ adst) {
    __shared__ float  Ws[F_IN * HC];
    __shared__ float4 xs[8][F_IN];
    __shared__ float  as_s[HC], ad_s[HC];

    int tid = threadIdx.x;
    for (int i = tid; i < F_IN * HC; i += 256) Ws[i] = W[i];
    if (tid < HC) { as_s[tid] = asrc[tid]; ad_s[tid] = adst[tid]; }

    int warp = tid >> 5, lane = tid & 31;
    int n0 = blockIdx.x * 32 + warp * 4;

    for (int k = lane; k < F_IN; k += 32) {
        float4 v;
        v.x = x[(n0 + 0) * F_IN + k];
        v.y = x[(n0 + 1) * F_IN + k];
        v.z = x[(n0 + 2) * F_IN + k];
        v.w = x[(n0 + 3) * F_IN + k];
        xs[warp][k] = v;
    }
    __syncthreads();

    float a00 = 0, a01 = 0, a10 = 0, a11 = 0, a20 = 0, a21 = 0, a30 = 0, a31 = 0;
    const float2* W2p = (const float2*)Ws;
#pragma unroll 8
    for (int k = 0; k < F_IN; k++) {
        float4 xv = xs[warp][k];
        float2 wv = W2p[k * 32 + lane];
        a00 += xv.x * wv.x; a01 += xv.x * wv.y;
        a10 += xv.y * wv.x; a11 += xv.y * wv.y;
        a20 += xv.z * wv.x; a21 += xv.z * wv.y;
        a30 += xv.w * wv.x; a31 += xv.w * wv.y;
    }

    int j0 = lane * 2;
    float asx = as_s[j0], asy = as_s[j0 + 1];
    float adx = ad_s[j0], ady = ad_s[j0 + 1];

#define EMIT(E, A0, A1)                                                          \
    {                                                                            \
        int n = n0 + (E);                                                        \
        g_h1h[n * 32 + lane] = __floats2half2_rn((A0), (A1));                    \
        float ps = (A0) * asx + (A1) * asy;                                      \
        float pd = (A0) * adx + (A1) * ady;                                      \
        ps += __shfl_xor_sync(0xffffffffu, ps, 1);                               \
        ps += __shfl_xor_sync(0xffffffffu, ps, 2);                               \
        pd += __shfl_xor_sync(0xffffffffu, pd, 1);                               \
        pd += __shfl_xor_sync(0xffffffffu, pd, 2);                               \
        if ((lane & 3) == 0) {                                                   \
            g_as1[n * HEADS + (lane >> 2)] = ps;                                 \
            g_ad1[n * HEADS + (lane >> 2)] = pd;                                 \
        }                                                                        \
    }
    EMIT(0, a00, a01) EMIT(1, a10, a11) EMIT(2, a20, a21) EMIT(3, a30, a31)
#undef EMIT
}

// ---------------- layer 1 aggregation + fused layer-2 GEMM ------------------
// warp per node; lane l owns head hl=(l&7), half2 index hidx=hl*4+(l>>3)
// (channels c0=hl*8+(l>>3)*2). After aggregation the warp holds the full
// activated o1 row -> compute h2 = o1 @ W2 and layer-2 logits in-warp.
__global__ void __launch_bounds__(256) edge1_fused(const float* __restrict__ b1,
                                                   const float* __restrict__ W2,
                                                   const float* __restrict__ as2v,
                                                   const float* __restrict__ ad2v) {
    __shared__ float Ws2[HC * NCLS];          // 10 KB
    __shared__ float a2s[NCLS], a2d[NCLS];
    __shared__ float hs[8][HC];

    int tid = threadIdx.x;
    for (int i = tid; i < HC * NCLS; i += 256) Ws2[i] = W2[i];
    if (tid < NCLS) { a2s[tid] = as2v[tid]; a2d[tid] = ad2v[tid]; }
    __syncthreads();

    int warp = tid >> 5, lane = tid & 31;
    int n = blockIdx.x * 8 + warp;
    if (n >= N_NODES) return;
    int hl = lane & 7;
    int hidx = hl * 4 + (lane >> 3);
    int c0 = hl * 8 + (lane >> 3) * 2;

    float ad = g_ad1[n * 8 + hl];
    float den = 0.f;
    float2 acc = make_float2(0.f, 0.f);

    int k = g_off[n], end = g_off[n + 1];
    while (k < end) {
        int cnt = min(32, end - k);
        int sv = (lane < cnt) ? g_csr_src[k + lane] : 0;
        int j = 0;
        for (; j + 8 <= cnt; j += 8) {
            int s[8]; float t[8]; __half2 hh[8];
#pragma unroll
            for (int u = 0; u < 8; u++) s[u] = __shfl_sync(0xffffffffu, sv, j + u);
#pragma unroll
            for (int u = 0; u < 8; u++) {
                t[u]  = g_as1[s[u] * 8 + hl];
                hh[u] = g_h1h[s[u] * 32 + hidx];
            }
#pragma unroll
            for (int u = 0; u < 8; u++) {
                float e = __expf(lrelu(t[u] + ad));
                float2 hv = __half22float2(hh[u]);
                den += e;
                acc.x += e * hv.x;
                acc.y += e * hv.y;
            }
        }
        for (; j < cnt; j++) {
            int s = __shfl_sync(0xffffffffu, sv, j);
            float e = __expf(lrelu(g_as1[s * 8 + hl] + ad));
            float2 hv = __half22float2(g_h1h[s * 32 + hidx]);
            den += e;
            acc.x += e * hv.x;
            acc.y += e * hv.y;
        }
        k += cnt;
    }

    float2 bias = *(const float2*)(b1 + c0);
    float inv = 1.f / (den + 1e-16f);
    float rx = fmaxf(acc.x * inv + bias.x, 0.f);   // bias + ReLU fused
    float ry = fmaxf(acc.y * inv + bias.y, 0.f);
    hs[warp][c0]     = rx;
    hs[warp][c0 + 1] = ry;
    __syncwarp();

    // ---- fused layer-2 GEMM: h2[n] = o1[n] @ W2, logits via warp reduce ----
    float acc0 = 0.f, acc1 = 0.f;
    int l8 = 32 + (lane & 7);
#pragma unroll 8
    for (int q = 0; q < HC; q++) {
        float hv = hs[warp][q];
        acc0 += hv * Ws2[q * NCLS + lane];
        acc1 += hv * Ws2[q * NCLS + l8];
    }

    __half* h2p = (__half*)g_h2h;
    h2p[n * NCLS + lane] = __float2half_rn(acc0);
    if (lane < 8) h2p[n * NCLS + 32 + lane] = __float2half_rn(acc1);

    float ps = acc0 * a2s[lane] + (lane < 8 ? acc1 * a2s[32 + lane] : 0.f);
    float pd = acc0 * a2d[lane] + (lane < 8 ? acc1 * a2d[32 + lane] : 0.f);
#pragma unroll
    for (int o = 16; o; o >>= 1) {
        ps += __shfl_xor_sync(0xffffffffu, ps, o);
        pd += __shfl_xor_sync(0xffffffffu, pd, o);
    }
    if (lane == 0) { g_as2[n] = ps; g_ad2[n] = pd; }
}

// ---------------- layer 2 CSR aggregation ------------------------------------
// lane l<20 owns classes 2l, 2l+1 (one half2).
__global__ void __launch_bounds__(256) edge_csr2(float* __restrict__ out,
                                                 const float* __restrict__ b2) {
    int warp = (blockIdx.x * 256 + threadIdx.x) >> 5;
    int l = threadIdx.x & 31;
    if (warp >= N_NODES) return;
    int n = warp;
    bool act = l < 20;
    int li = act ? l : 0;

    float ad = g_ad2[n];
    float den = 0.f;
    float2 acc = make_float2(0.f, 0.f);

    int k = g_off[n], end = g_off[n + 1];
    while (k < end) {
        int cnt = min(32, end - k);
        int sv = (l < cnt) ? g_csr_src[k + l] : 0;
        int j = 0;
        for (; j + 8 <= cnt; j += 8) {
            int s[8]; float t[8]; __half2 hh[8];
#pragma unroll
            for (int u = 0; u < 8; u++) s[u] = __shfl_sync(0xffffffffu, sv, j + u);
#pragma unroll
            for (int u = 0; u < 8; u++) {
                t[u]  = g_as2[s[u]];
                hh[u] = g_h2h[s[u] * 20 + li];
            }
#pragma unroll
            for (int u = 0; u < 8; u++) {
                float e = __expf(lrelu(t[u] + ad));
                float2 hv = __half22float2(hh[u]);
                den += e;
                acc.x += e * hv.x;
                acc.y += e * hv.y;
            }
        }
        for (; j < cnt; j++) {
            int s = __shfl_sync(0xffffffffu, sv, j);
            float e = __expf(lrelu(g_as2[s] + ad));
            float2 hv = __half22float2(g_h2h[s * 20 + li]);
            den += e;
            acc.x += e * hv.x;
            acc.y += e * hv.y;
        }
        k += cnt;
    }

    if (act) {
        float2 bias = *(const float2*)(b2 + l * 2);
        float inv = 1.f / (den + 1e-16f);
        float2 r;
        r.x = acc.x * inv + bias.x;
        r.y = acc.y * inv + bias.y;
        *(float2*)(out + n * NCLS + l * 2) = r;
    }
}

// ---------------- launch -----------------------------------------------------
extern "C" void kernel_launch(void* const* d_in, const int* in_sizes, int n_in,
                              void* d_out, int out_size) {
    const float* x   = (const float*)d_in[0];
    const void*  ei  = d_in[1];
    const float* W1  = (const float*)d_in[2];
    const float* as1 = (const float*)d_in[3];
    const float* ad1 = (const float*)d_in[4];
    const float* b1  = (const float*)d_in[5];
    const float* W2  = (const float*)d_in[6];
    const float* as2 = (const float*)d_in[7];
    const float* ad2 = (const float*)d_in[8];
    const float* b2  = (const float*)d_in[9];
    float*       out = (float*)d_out;

    // ---- CSR build ----
    probe_zero<<<(N_NODES + 256) / 256, 256>>>((const long long*)ei);
    hist_dst<<<((unsigned)TOT_E + 255) / 256, 256>>>(ei);
    scan_blocks<<<NB_SCAN, 1024>>>();
    fixup_offsets<<<(N_NODES + 256) / 256, 256>>>();
    scatter_csr<<<((unsigned)TOT_E + 255) / 256, 256>>>(ei);

    // ---- layer 1 (+ fused layer-2 GEMM) ----
    gemm1<<<N_NODES / 32, 256>>>(x, W1, as1, ad1);
    edge1_fused<<<(N_NODES + 7) / 8, 256>>>(b1, W2, as2, ad2);

    // ---- layer 2 ----
    edge_csr2<<<(N_NODES * 32 + 255) / 256, 256>>>(out, b2);
}

// round 7
// speedup vs baseline: 1.8430x; 1.0654x over previous
#include <cuda_runtime.h>
#include <cuda_fp16.h>

#define N_NODES 100000
#define N_EDGES 1600000
#define TOT_E   (N_EDGES + N_NODES)   // edges + self loops
#define F_IN    128
#define HEADS   8
#define HID     8
#define HC      64
#define NCLS    40
#define NEG_SLOPE 0.2f
#define NB_SCAN 98                     // ceil((N_NODES+1)/1024)

// ---------------- scratch (static device globals) ---------------------------
__device__ __align__(16) __half2 g_h1h[N_NODES * 32];   // layer1 features, fp16 pairs
__device__ float g_as1[N_NODES * HEADS];
__device__ float g_ad1[N_NODES * HEADS];
__device__ __align__(16) __half2 g_h2h[N_NODES * 20];   // layer2 features, fp16 pairs
__device__ float g_as2[N_NODES];
__device__ float g_ad2[N_NODES];
__device__ int  g_csr_src[TOT_E];
__device__ int  g_deg[N_NODES + 1];
__device__ int  g_off[N_NODES + 1];
__device__ int  g_pos[N_NODES];
__device__ int  g_bsum[NB_SCAN];
__device__ int  g_is64;

__device__ __forceinline__ float lrelu(float x) { return x > 0.f ? x : NEG_SLOPE * x; }

// ---------------- probe dtype + zero degree array ---------------------------
__global__ void probe_zero(const long long* __restrict__ ei) {
    unsigned i = blockIdx.x * 256u + threadIdx.x;
    if (i <= N_NODES) g_deg[i] = 0;
    if (blockIdx.x == 0 && threadIdx.x < 32) {
        int l = threadIdx.x;
        int bad = 0;
#pragma unroll
        for (int k = 0; k < 8; k++) {
            long long v = ei[l * 8 + k];
            if (v < 0 || v >= (long long)N_NODES) bad = 1;
        }
        unsigned m = __ballot_sync(0xffffffffu, bad);
        if (l == 0) g_is64 = (m == 0u);
    }
}

__global__ void hist_dst(const void* __restrict__ ei) {
    unsigned e = blockIdx.x * 256u + threadIdx.x;
    if (e >= (unsigned)TOT_E) return;
    int d;
    if (e < (unsigned)N_EDGES) {
        d = g_is64 ? (int)((const long long*)ei)[N_EDGES + e]
                   : ((const int*)ei)[N_EDGES + e];
    } else {
        d = (int)(e - (unsigned)N_EDGES);
    }
    atomicAdd(&g_deg[d], 1);
}

__global__ void __launch_bounds__(1024) scan_blocks() {
    __shared__ int sh[1024];
    int t = threadIdx.x;
    unsigned i = blockIdx.x * 1024u + t;
    int v = (i <= N_NODES) ? g_deg[i] : 0;
    sh[t] = v; __syncthreads();
#pragma unroll
    for (int off = 1; off < 1024; off <<= 1) {
        int add = (t >= off) ? sh[t - off] : 0;
        __syncthreads();
        sh[t] += add;
        __syncthreads();
    }
    if (i <= N_NODES) g_off[i] = sh[t] - v;
    if (t == 1023) g_bsum[blockIdx.x] = sh[t];
}

__global__ void __launch_bounds__(256) fixup_offsets() {
    __shared__ int sb[128];
    int t = threadIdx.x;
    if (t < 128) sb[t] = (t < NB_SCAN) ? g_bsum[t] : 0;
    __syncthreads();
#pragma unroll
    for (int off = 1; off < 128; off <<= 1) {
        int add = (t < 128 && t >= off) ? sb[t - off] : 0;
        __syncthreads();
        if (t < 128) sb[t] += add;
        __syncthreads();
    }
    unsigned i = blockIdx.x * 256u + t;
    if (i > N_NODES) return;
    unsigned b = i >> 10;
    int pre = (b == 0) ? 0 : sb[b - 1];       // exclusive
    int o = g_off[i] + pre;
    g_off[i] = o;
    if (i < N_NODES) g_pos[i] = o;
}

__global__ void scatter_csr(const void* __restrict__ ei) {
    unsigned e = blockIdx.x * 256u + threadIdx.x;
    if (e >= (unsigned)TOT_E) return;
    int s, d;
    if (e < (unsigned)N_EDGES) {
        if (g_is64) {
            const long long* p = (const long long*)ei;
            s = (int)p[e]; d = (int)p[N_EDGES + e];
        } else {
            const int* p = (const int*)ei;
            s = p[e]; d = p[N_EDGES + e];
        }
    } else {
        s = d = (int)(e - (unsigned)N_EDGES);
    }
    int p = atomicAdd(&g_pos[d], 1);
    g_csr_src[p] = s;
}

// ---------------- layer 1 GEMM + attention logits ---------------------------
__global__ void __launch_bounds__(256) gemm1(const float* __restrict__ x,
                                             const float* __restrict__ W,
                                             const float* __restrict__ asrc,
                                             const float* __restrict__ adst) {
    __shared__ float  Ws[F_IN * HC];
    __shared__ float4 xs[8][F_IN];
    __shared__ float  as_s[HC], ad_s[HC];

    int tid = threadIdx.x;
    for (int i = tid; i < F_IN * HC; i += 256) Ws[i] = W[i];
    if (tid < HC) { as_s[tid] = asrc[tid]; ad_s[tid] = adst[tid]; }

    int warp = tid >> 5, lane = tid & 31;
    int n0 = blockIdx.x * 32 + warp * 4;

    for (int k = lane; k < F_IN; k += 32) {
        float4 v;
        v.x = x[(n0 + 0) * F_IN + k];
        v.y = x[(n0 + 1) * F_IN + k];
        v.z = x[(n0 + 2) * F_IN + k];
        v.w = x[(n0 + 3) * F_IN + k];
        xs[warp][k] = v;
    }
    __syncthreads();

    float a00 = 0, a01 = 0, a10 = 0, a11 = 0, a20 = 0, a21 = 0, a30 = 0, a31 = 0;
    const float2* W2p = (const float2*)Ws;
#pragma unroll 8
    for (int k = 0; k < F_IN; k++) {
        float4 xv = xs[warp][k];
        float2 wv = W2p[k * 32 + lane];
        a00 += xv.x * wv.x; a01 += xv.x * wv.y;
        a10 += xv.y * wv.x; a11 += xv.y * wv.y;
        a20 += xv.z * wv.x; a21 += xv.z * wv.y;
        a30 += xv.w * wv.x; a31 += xv.w * wv.y;
    }

    int j0 = lane * 2;
    float asx = as_s[j0], asy = as_s[j0 + 1];
    float adx = ad_s[j0], ady = ad_s[j0 + 1];

#define EMIT(E, A0, A1)                                                          \
    {                                                                            \
        int n = n0 + (E);                                                        \
        g_h1h[n * 32 + lane] = __floats2half2_rn((A0), (A1));                    \
        float ps = (A0) * asx + (A1) * asy;                                      \
        float pd = (A0) * adx + (A1) * ady;                                      \
        ps += __shfl_xor_sync(0xffffffffu, ps, 1);                               \
        ps += __shfl_xor_sync(0xffffffffu, ps, 2);                               \
        pd += __shfl_xor_sync(0xffffffffu, pd, 1);                               \
        pd += __shfl_xor_sync(0xffffffffu, pd, 2);                               \
        if ((lane & 3) == 0) {                                                   \
            g_as1[n * HEADS + (lane >> 2)] = ps;                                 \
            g_ad1[n * HEADS + (lane >> 2)] = pd;                                 \
        }                                                                        \
    }
    EMIT(0, a00, a01) EMIT(1, a10, a11) EMIT(2, a20, a21) EMIT(3, a30, a31)
#undef EMIT
}

// ---------------- layer 1 aggregation (2 edges/warp-step) + fused gemm2 -----
// Warp per node. Lanes split by parity p=lane>>4 over edge pairs; sub-lane
// q=lane&15 owns head hl=q>>1 and 4 channels c0=hl*8+(q&1)*4 (one 8B uint2
// of half2s). Cross-parity shfl_xor(16) reduce at the end.
__global__ void __launch_bounds__(256) edge1_fused(const float* __restrict__ b1,
                                                   const float* __restrict__ W2,
                                                   const float* __restrict__ as2v,
                                                   const float* __restrict__ ad2v) {
    __shared__ float Ws2[HC * NCLS];          // 10 KB
    __shared__ float a2s[NCLS], a2d[NCLS];
    __shared__ float hs[8][HC];

    int tid = threadIdx.x;
    for (int i = tid; i < HC * NCLS; i += 256) Ws2[i] = W2[i];
    if (tid < NCLS) { a2s[tid] = as2v[tid]; a2d[tid] = ad2v[tid]; }
    __syncthreads();

    int warp = tid >> 5, lane = tid & 31;
    int n = blockIdx.x * 8 + warp;
    if (n >= N_NODES) return;
    int q = lane & 15, p = lane >> 4;
    int hl = q >> 1;                          // head
    int h2i = hl * 4 + (q & 1) * 2;           // half2 base index in node row
    int c0 = hl * 8 + (q & 1) * 4;            // float channel base

    float ad = g_ad1[n * 8 + hl];
    float den = 0.f;
    float4 acc = make_float4(0.f, 0.f, 0.f, 0.f);

    int k = g_off[n], end = g_off[n + 1];
    while (k < end) {
        int cnt = min(32, end - k);
        int sv = (lane < cnt) ? g_csr_src[k + lane] : 0;
        int j = 0;
        // unrolled: 4 pairs = 8 edges; all indices j+p..j+6+p < cnt guaranteed
        for (; j + 8 <= cnt; j += 8) {
            int s[4]; float t[4]; uint2 hw[4];
#pragma unroll
            for (int u = 0; u < 4; u++) s[u] = __shfl_sync(0xffffffffu, sv, j + 2 * u + p);
#pragma unroll
            for (int u = 0; u < 4; u++) {
                t[u]  = g_as1[s[u] * 8 + hl];
                hw[u] = *(const uint2*)(g_h1h + s[u] * 32 + h2i);
            }
#pragma unroll
            for (int u = 0; u < 4; u++) {
                float e = __expf(lrelu(t[u] + ad));
                float2 ha = __half22float2(*(__half2*)&hw[u].x);
                float2 hb = __half22float2(*(__half2*)&hw[u].y);
                den += e;
                acc.x += e * ha.x; acc.y += e * ha.y;
                acc.z += e * hb.x; acc.w += e * hb.y;
            }
        }
        for (; j < cnt; j += 2) {
            int je = j + p;
            bool v = je < cnt;
            int s = __shfl_sync(0xffffffffu, sv, je & 31);
            float t = g_as1[s * 8 + hl];
            uint2 hw = *(const uint2*)(g_h1h + s * 32 + h2i);
            float e = v ? __expf(lrelu(t + ad)) : 0.f;
            float2 ha = __half22float2(*(__half2*)&hw.x);
            float2 hb = __half22float2(*(__half2*)&hw.y);
            den += e;
            acc.x += e * ha.x; acc.y += e * ha.y;
            acc.z += e * hb.x; acc.w += e * hb.y;
        }
        k += cnt;
    }

    // combine parity halves (lane l and l^16 own identical channels)
    den   += __shfl_xor_sync(0xffffffffu, den,   16);
    acc.x += __shfl_xor_sync(0xffffffffu, acc.x, 16);
    acc.y += __shfl_xor_sync(0xffffffffu, acc.y, 16);
    acc.z += __shfl_xor_sync(0xffffffffu, acc.z, 16);
    acc.w += __shfl_xor_sync(0xffffffffu, acc.w, 16);

    float4 bias = *(const float4*)(b1 + c0);
    float inv = 1.f / (den + 1e-16f);
    hs[warp][c0]     = fmaxf(acc.x * inv + bias.x, 0.f);
    hs[warp][c0 + 1] = fmaxf(acc.y * inv + bias.y, 0.f);
    hs[warp][c0 + 2] = fmaxf(acc.z * inv + bias.z, 0.f);
    hs[warp][c0 + 3] = fmaxf(acc.w * inv + bias.w, 0.f);
    __syncwarp();

    // ---- fused layer-2 GEMM: h2[n] = o1[n] @ W2, logits via warp reduce ----
    float acc0 = 0.f, acc1 = 0.f;
    int l8 = 32 + (lane & 7);
#pragma unroll 8
    for (int w = 0; w < HC; w++) {
        float hv = hs[warp][w];
        acc0 += hv * Ws2[w * NCLS + lane];
        acc1 += hv * Ws2[w * NCLS + l8];
    }

    __half* h2p = (__half*)g_h2h;
    h2p[n * NCLS + lane] = __float2half_rn(acc0);
    if (lane < 8) h2p[n * NCLS + 32 + lane] = __float2half_rn(acc1);

    float ps = acc0 * a2s[lane] + (lane < 8 ? acc1 * a2s[32 + lane] : 0.f);
    float pd = acc0 * a2d[lane] + (lane < 8 ? acc1 * a2d[32 + lane] : 0.f);
#pragma unroll
    for (int o = 16; o; o >>= 1) {
        ps += __shfl_xor_sync(0xffffffffu, ps, o);
        pd += __shfl_xor_sync(0xffffffffu, pd, o);
    }
    if (lane == 0) { g_as2[n] = ps; g_ad2[n] = pd; }
}

// ---------------- layer 2 CSR aggregation ------------------------------------
__global__ void __launch_bounds__(256) edge_csr2(float* __restrict__ out,
                                                 const float* __restrict__ b2) {
    int warp = (blockIdx.x * 256 + threadIdx.x) >> 5;
    int l = threadIdx.x & 31;
    if (warp >= N_NODES) return;
    int n = warp;
    bool act = l < 20;
    int li = act ? l : 0;

    float ad = g_ad2[n];
    float den = 0.f;
    float2 acc = make_float2(0.f, 0.f);

    int k = g_off[n], end = g_off[n + 1];
    while (k < end) {
        int cnt = min(32, end - k);
        int sv = (l < cnt) ? g_csr_src[k + l] : 0;
        int j = 0;
        for (; j + 8 <= cnt; j += 8) {
            int s[8]; float t[8]; __half2 hh[8];
#pragma unroll
            for (int u = 0; u < 8; u++) s[u] = __shfl_sync(0xffffffffu, sv, j + u);
#pragma unroll
            for (int u = 0; u < 8; u++) {
                t[u]  = g_as2[s[u]];
                hh[u] = g_h2h[s[u] * 20 + li];
            }
#pragma unroll
            for (int u = 0; u < 8; u++) {
                float e = __expf(lrelu(t[u] + ad));
                float2 hv = __half22float2(hh[u]);
                den += e;
                acc.x += e * hv.x;
                acc.y += e * hv.y;
            }
        }
        for (; j < cnt; j++) {
            int s = __shfl_sync(0xffffffffu, sv, j);
            float e = __expf(lrelu(g_as2[s] + ad));
            float2 hv = __half22float2(g_h2h[s * 20 + li]);
            den += e;
            acc.x += e * hv.x;
            acc.y += e * hv.y;
        }
        k += cnt;
    }

    if (act) {
        float2 bias = *(const float2*)(b2 + l * 2);
        float inv = 1.f / (den + 1e-16f);
        float2 r;
        r.x = acc.x * inv + bias.x;
        r.y = acc.y * inv + bias.y;
        *(float2*)(out + n * NCLS + l * 2) = r;
    }
}

// ---------------- launch -----------------------------------------------------
extern "C" void kernel_launch(void* const* d_in, const int* in_sizes, int n_in,
                              void* d_out, int out_size) {
    const float* x   = (const float*)d_in[0];
    const void*  ei  = d_in[1];
    const float* W1  = (const float*)d_in[2];
    const float* as1 = (const float*)d_in[3];
    const float* ad1 = (const float*)d_in[4];
    const float* b1  = (const float*)d_in[5];
    const float* W2  = (const float*)d_in[6];
    const float* as2 = (const float*)d_in[7];
    const float* ad2 = (const float*)d_in[8];
    const float* b2  = (const float*)d_in[9];
    float*       out = (float*)d_out;

    // fork: CSR build on side stream, gemm1 concurrently on main stream
    cudaStream_t s1;
    cudaStreamCreateWithFlags(&s1, cudaStreamNonBlocking);
    cudaEvent_t ev0, ev1;
    cudaEventCreateWithFlags(&ev0, cudaEventDisableTiming);
    cudaEventCreateWithFlags(&ev1, cudaEventDisableTiming);

    cudaEventRecord(ev0, 0);
    cudaStreamWaitEvent(s1, ev0, 0);

    // ---- CSR build (side stream) ----
    probe_zero<<<(N_NODES + 256) / 256, 256, 0, s1>>>((const long long*)ei);
    hist_dst<<<((unsigned)TOT_E + 255) / 256, 256, 0, s1>>>(ei);
    scan_blocks<<<NB_SCAN, 1024, 0, s1>>>();
    fixup_offsets<<<(N_NODES + 256) / 256, 256, 0, s1>>>();
    scatter_csr<<<((unsigned)TOT_E + 255) / 256, 256, 0, s1>>>(ei);
    cudaEventRecord(ev1, s1);

    // ---- layer 1 GEMM (main stream, overlapped) ----
    gemm1<<<N_NODES / 32, 256>>>(x, W1, as1, ad1);

    // join
    cudaStreamWaitEvent(0, ev1, 0);

    // ---- layer 1 aggregation + fused layer-2 GEMM ----
    edge1_fused<<<(N_NODES + 7) / 8, 256>>>(b1, W2, as2, ad2);

    // ---- layer 2 ----
    edge_csr2<<<(N_NODES * 32 + 255) / 256, 256>>>(out, b2);

    cudaEventDestroy(ev0);
    cudaEventDestroy(ev1);
    cudaStreamDestroy(s1);
}

// round 8
// speedup vs baseline: 1.9263x; 1.0452x over previous
#include <cuda_runtime.h>
#include <cuda_fp16.h>

#define N_NODES 100000
#define N_EDGES 1600000
#define TOT_E   (N_EDGES + N_NODES)   // edges + self loops
#define F_IN    128
#define HEADS   8
#define HID     8
#define HC      64
#define NCLS    40
#define NEG_SLOPE 0.2f
#define NB_SCAN 98                     // ceil((N_NODES+1)/1024)

// ---------------- scratch (static device globals) ---------------------------
__device__ __align__(16) __half2 g_h1h[N_NODES * 32];   // layer1 features, fp16 pairs
__device__ float g_as1[N_NODES * HEADS];
__device__ float g_ad1[N_NODES * HEADS];
__device__ __align__(16) __half2 g_h2h[N_NODES * 20];   // layer2 features, fp16 pairs
__device__ float g_as2[N_NODES];
__device__ float g_ad2[N_NODES];
__device__ int  g_csr_src[TOT_E];
__device__ int  g_deg[N_NODES + 1];
__device__ int  g_off[N_NODES + 1];
__device__ int  g_pos[N_NODES];
__device__ int  g_bsum[NB_SCAN];
__device__ int  g_is64;

__device__ __forceinline__ float lrelu(float x) { return x > 0.f ? x : NEG_SLOPE * x; }

// ---------------- probe dtype + zero degree array ---------------------------
__global__ void probe_zero(const long long* __restrict__ ei) {
    unsigned i = blockIdx.x * 256u + threadIdx.x;
    if (i <= N_NODES) g_deg[i] = 0;
    if (blockIdx.x == 0 && threadIdx.x < 32) {
        int l = threadIdx.x;
        int bad = 0;
#pragma unroll
        for (int k = 0; k < 8; k++) {
            long long v = ei[l * 8 + k];
            if (v < 0 || v >= (long long)N_NODES) bad = 1;
        }
        unsigned m = __ballot_sync(0xffffffffu, bad);
        if (l == 0) g_is64 = (m == 0u);
    }
}

__global__ void hist_dst(const void* __restrict__ ei) {
    unsigned e = blockIdx.x * 256u + threadIdx.x;
    if (e >= (unsigned)TOT_E) return;
    int d;
    if (e < (unsigned)N_EDGES) {
        d = g_is64 ? (int)((const long long*)ei)[N_EDGES + e]
                   : ((const int*)ei)[N_EDGES + e];
    } else {
        d = (int)(e - (unsigned)N_EDGES);
    }
    atomicAdd(&g_deg[d], 1);
}

__global__ void __launch_bounds__(1024) scan_blocks() {
    __shared__ int sh[1024];
    int t = threadIdx.x;
    unsigned i = blockIdx.x * 1024u + t;
    int v = (i <= N_NODES) ? g_deg[i] : 0;
    sh[t] = v; __syncthreads();
#pragma unroll
    for (int off = 1; off < 1024; off <<= 1) {
        int add = (t >= off) ? sh[t - off] : 0;
        __syncthreads();
        sh[t] += add;
        __syncthreads();
    }
    if (i <= N_NODES) g_off[i] = sh[t] - v;
    if (t == 1023) g_bsum[blockIdx.x] = sh[t];
}

__global__ void __launch_bounds__(256) fixup_offsets() {
    __shared__ int sb[128];
    int t = threadIdx.x;
    if (t < 128) sb[t] = (t < NB_SCAN) ? g_bsum[t] : 0;
    __syncthreads();
#pragma unroll
    for (int off = 1; off < 128; off <<= 1) {
        int add = (t < 128 && t >= off) ? sb[t - off] : 0;
        __syncthreads();
        if (t < 128) sb[t] += add;
        __syncthreads();
    }
    unsigned i = blockIdx.x * 256u + t;
    if (i > N_NODES) return;
    unsigned b = i >> 10;
    int pre = (b == 0) ? 0 : sb[b - 1];       // exclusive
    int o = g_off[i] + pre;
    g_off[i] = o;
    if (i < N_NODES) g_pos[i] = o;
}

__global__ void scatter_csr(const void* __restrict__ ei) {
    unsigned e = blockIdx.x * 256u + threadIdx.x;
    if (e >= (unsigned)TOT_E) return;
    int s, d;
    if (e < (unsigned)N_EDGES) {
        if (g_is64) {
            const long long* p = (const long long*)ei;
            s = (int)p[e]; d = (int)p[N_EDGES + e];
        } else {
            const int* p = (const int*)ei;
            s = p[e]; d = p[N_EDGES + e];
        }
    } else {
        s = d = (int)(e - (unsigned)N_EDGES);
    }
    int p = atomicAdd(&g_pos[d], 1);
    g_csr_src[p] = s;
}

// ---------------- layer 1 GEMM + attention logits ---------------------------
__global__ void __launch_bounds__(256) gemm1(const float* __restrict__ x,
                                             const float* __restrict__ W,
                                             const float* __restrict__ asrc,
                                             const float* __restrict__ adst) {
    __shared__ float  Ws[F_IN * HC];
    __shared__ float4 xs[8][F_IN];
    __shared__ float  as_s[HC], ad_s[HC];

    int tid = threadIdx.x;
    for (int i = tid; i < F_IN * HC; i += 256) Ws[i] = W[i];
    if (tid < HC) { as_s[tid] = asrc[tid]; ad_s[tid] = adst[tid]; }

    int warp = tid >> 5, lane = tid & 31;
    int n0 = blockIdx.x * 32 + warp * 4;

    for (int k = lane; k < F_IN; k += 32) {
        float4 v;
        v.x = x[(n0 + 0) * F_IN + k];
        v.y = x[(n0 + 1) * F_IN + k];
        v.z = x[(n0 + 2) * F_IN + k];
        v.w = x[(n0 + 3) * F_IN + k];
        xs[warp][k] = v;
    }
    __syncthreads();

    float a00 = 0, a01 = 0, a10 = 0, a11 = 0, a20 = 0, a21 = 0, a30 = 0, a31 = 0;
    const float2* W2p = (const float2*)Ws;
#pragma unroll 8
    for (int k = 0; k < F_IN; k++) {
        float4 xv = xs[warp][k];
        float2 wv = W2p[k * 32 + lane];
        a00 += xv.x * wv.x; a01 += xv.x * wv.y;
        a10 += xv.y * wv.x; a11 += xv.y * wv.y;
        a20 += xv.z * wv.x; a21 += xv.z * wv.y;
        a30 += xv.w * wv.x; a31 += xv.w * wv.y;
    }

    int j0 = lane * 2;
    float asx = as_s[j0], asy = as_s[j0 + 1];
    float adx = ad_s[j0], ady = ad_s[j0 + 1];

#define EMIT(E, A0, A1)                                                          \
    {                                                                            \
        int n = n0 + (E);                                                        \
        g_h1h[n * 32 + lane] = __floats2half2_rn((A0), (A1));                    \
        float ps = (A0) * asx + (A1) * asy;                                      \
        float pd = (A0) * adx + (A1) * ady;                                      \
        ps += __shfl_xor_sync(0xffffffffu, ps, 1);                               \
        ps += __shfl_xor_sync(0xffffffffu, ps, 2);                               \
        pd += __shfl_xor_sync(0xffffffffu, pd, 1);                               \
        pd += __shfl_xor_sync(0xffffffffu, pd, 2);                               \
        if ((lane & 3) == 0) {                                                   \
            g_as1[n * HEADS + (lane >> 2)] = ps;                                 \
            g_ad1[n * HEADS + (lane >> 2)] = pd;                                 \
        }                                                                        \
    }
    EMIT(0, a00, a01) EMIT(1, a10, a11) EMIT(2, a20, a21) EMIT(3, a30, a31)
#undef EMIT
}

// ---------------- layer 1 aggregation (4 edges/warp-step) + fused gemm2 -----
// Warp per node. Lane = group p=lane>>3 (edge slot) x sub-lane q=lane&7 (head).
// Lane owns head q's 8 channels via one uint4 (16B); 4 edges retired per step.
// Per-head denominators are natural (lane q's exp IS head q's). Cross-group
// reduce via shfl_xor 8,16.
__global__ void __launch_bounds__(256) edge1_fused(const float* __restrict__ b1,
                                                   const float* __restrict__ W2,
                                                   const float* __restrict__ as2v,
                                                   const float* __restrict__ ad2v) {
    __shared__ float Ws2[HC * NCLS];          // 10 KB
    __shared__ float a2s[NCLS], a2d[NCLS];
    __shared__ float hs[8][HC];

    int tid = threadIdx.x;
    for (int i = tid; i < HC * NCLS; i += 256) Ws2[i] = W2[i];
    if (tid < NCLS) { a2s[tid] = as2v[tid]; a2d[tid] = ad2v[tid]; }
    __syncthreads();

    int warp = tid >> 5, lane = tid & 31;
    int n = blockIdx.x * 8 + warp;
    if (n >= N_NODES) return;
    int q = lane & 7;                          // head
    int p = lane >> 3;                         // edge slot 0..3

    float ad = g_ad1[n * 8 + q];
    float den = 0.f;
    float a0 = 0.f, a1 = 0.f, a2 = 0.f, a3 = 0.f,
          a4 = 0.f, a5 = 0.f, a6 = 0.f, a7 = 0.f;

    int k = g_off[n], end = g_off[n + 1];
    while (k < end) {
        int cnt = min(32, end - k);
        int sv = (lane < cnt) ? g_csr_src[k + lane] : 0;
        int j = 0;
        for (; j + 8 <= cnt; j += 8) {        // 2 edges per lane, 8 per warp
            int s0 = __shfl_sync(0xffffffffu, sv, j + p);
            int s1 = __shfl_sync(0xffffffffu, sv, j + 4 + p);
            float t0 = g_as1[s0 * 8 + q];
            float t1 = g_as1[s1 * 8 + q];
            uint4 h0 = *(const uint4*)(g_h1h + s0 * 32 + q * 4);
            uint4 h1 = *(const uint4*)(g_h1h + s1 * 32 + q * 4);
            float e0 = __expf(lrelu(t0 + ad));
            float e1 = __expf(lrelu(t1 + ad));
            den += e0 + e1;
            {
                float2 v0 = __half22float2(*(__half2*)&h0.x);
                float2 v1 = __half22float2(*(__half2*)&h0.y);
                float2 v2 = __half22float2(*(__half2*)&h0.z);
                float2 v3 = __half22float2(*(__half2*)&h0.w);
                a0 += e0 * v0.x; a1 += e0 * v0.y; a2 += e0 * v1.x; a3 += e0 * v1.y;
                a4 += e0 * v2.x; a5 += e0 * v2.y; a6 += e0 * v3.x; a7 += e0 * v3.y;
            }
            {
                float2 v0 = __half22float2(*(__half2*)&h1.x);
                float2 v1 = __half22float2(*(__half2*)&h1.y);
                float2 v2 = __half22float2(*(__half2*)&h1.z);
                float2 v3 = __half22float2(*(__half2*)&h1.w);
                a0 += e1 * v0.x; a1 += e1 * v0.y; a2 += e1 * v1.x; a3 += e1 * v1.y;
                a4 += e1 * v2.x; a5 += e1 * v2.y; a6 += e1 * v3.x; a7 += e1 * v3.y;
            }
        }
        for (; j < cnt; j += 4) {             // leftover: up to 4 edges
            int je = j + p;
            bool valid = je < cnt;
            int s = __shfl_sync(0xffffffffu, sv, je & 31);
            float t = g_as1[s * 8 + q];
            uint4 h = *(const uint4*)(g_h1h + s * 32 + q * 4);
            float e = valid ? __expf(lrelu(t + ad)) : 0.f;
            den += e;
            float2 v0 = __half22float2(*(__half2*)&h.x);
            float2 v1 = __half22float2(*(__half2*)&h.y);
            float2 v2 = __half22float2(*(__half2*)&h.z);
            float2 v3 = __half22float2(*(__half2*)&h.w);
            a0 += e * v0.x; a1 += e * v0.y; a2 += e * v1.x; a3 += e * v1.y;
            a4 += e * v2.x; a5 += e * v2.y; a6 += e * v3.x; a7 += e * v3.y;
        }
        k += cnt;
    }

    // combine the 4 edge-slot groups (bits 3 and 4 of lane)
#define RED(X) X += __shfl_xor_sync(0xffffffffu, X, 8); X += __shfl_xor_sync(0xffffffffu, X, 16);
    RED(den) RED(a0) RED(a1) RED(a2) RED(a3) RED(a4) RED(a5) RED(a6) RED(a7)
#undef RED

    if (p == 0) {
        int c0 = q * 8;
        float4 ba = *(const float4*)(b1 + c0);
        float4 bb = *(const float4*)(b1 + c0 + 4);
        float inv = 1.f / (den + 1e-16f);
        hs[warp][c0]     = fmaxf(a0 * inv + ba.x, 0.f);
        hs[warp][c0 + 1] = fmaxf(a1 * inv + ba.y, 0.f);
        hs[warp][c0 + 2] = fmaxf(a2 * inv + ba.z, 0.f);
        hs[warp][c0 + 3] = fmaxf(a3 * inv + ba.w, 0.f);
        hs[warp][c0 + 4] = fmaxf(a4 * inv + bb.x, 0.f);
        hs[warp][c0 + 5] = fmaxf(a5 * inv + bb.y, 0.f);
        hs[warp][c0 + 6] = fmaxf(a6 * inv + bb.z, 0.f);
        hs[warp][c0 + 7] = fmaxf(a7 * inv + bb.w, 0.f);
    }
    __syncwarp();

    // ---- fused layer-2 GEMM: h2[n] = o1[n] @ W2, logits via warp reduce ----
    float acc0 = 0.f, acc1 = 0.f;
    int l8 = 32 + (lane & 7);
#pragma unroll 8
    for (int w = 0; w < HC; w++) {
        float hv = hs[warp][w];
        acc0 += hv * Ws2[w * NCLS + lane];
        acc1 += hv * Ws2[w * NCLS + l8];
    }

    __half* h2p = (__half*)g_h2h;
    h2p[n * NCLS + lane] = __float2half_rn(acc0);
    if (lane < 8) h2p[n * NCLS + 32 + lane] = __float2half_rn(acc1);

    float ps = acc0 * a2s[lane] + (lane < 8 ? acc1 * a2s[32 + lane] : 0.f);
    float pd = acc0 * a2d[lane] + (lane < 8 ? acc1 * a2d[32 + lane] : 0.f);
#pragma unroll
    for (int o = 16; o; o >>= 1) {
        ps += __shfl_xor_sync(0xffffffffu, ps, o);
        pd += __shfl_xor_sync(0xffffffffu, pd, o);
    }
    if (lane == 0) { g_as2[n] = ps; g_ad2[n] = pd; }
}

// ---------------- layer 2 CSR aggregation (6 edges/warp-step) ----------------
// 6 groups of 5 lanes (lanes 0..29); group g handles edge j+g; lane t=lane%5
// owns classes [8t,8t+8) via one uint4. Tree-reduce across groups at the end.
__global__ void __launch_bounds__(256) edge_csr2(float* __restrict__ out,
                                                 const float* __restrict__ b2) {
    int warp = (blockIdx.x * 256 + threadIdx.x) >> 5;
    int lane = threadIdx.x & 31;
    if (warp >= N_NODES) return;
    int n = warp;
    int g = lane / 5;                          // group 0..5 (6 for lanes 30,31)
    int t = lane - g * 5;                      // sub-lane 0..4
    bool live = g < 6;
    int ti = live ? t : 0;

    float ad = g_ad2[n];
    float den = 0.f;
    float a0 = 0.f, a1 = 0.f, a2 = 0.f, a3 = 0.f,
          a4 = 0.f, a5 = 0.f, a6 = 0.f, a7 = 0.f;

    int k = g_off[n], end = g_off[n + 1];
    while (k < end) {
        int cnt = min(32, end - k);
        int sv = (lane < cnt) ? g_csr_src[k + lane] : 0;
        int j = 0;
        for (; j + 12 <= cnt; j += 12) {      // 2 edges per group, 12 per warp
            int s0 = __shfl_sync(0xffffffffu, sv, (j + g) & 31);
            int s1 = __shfl_sync(0xffffffffu, sv, (j + 6 + g) & 31);
            float t0 = g_as2[s0];
            float t1 = g_as2[s1];
            uint4 h0 = *(const uint4*)((const uint4*)g_h2h + s0 * 5 + ti);
            uint4 h1 = *(const uint4*)((const uint4*)g_h2h + s1 * 5 + ti);
            float e0 = live ? __expf(lrelu(t0 + ad)) : 0.f;
            float e1 = live ? __expf(lrelu(t1 + ad)) : 0.f;
            den += e0 + e1;
            {
                float2 v0 = __half22float2(*(__half2*)&h0.x);
                float2 v1 = __half22float2(*(__half2*)&h0.y);
                float2 v2 = __half22float2(*(__half2*)&h0.z);
                float2 v3 = __half22float2(*(__half2*)&h0.w);
                a0 += e0 * v0.x; a1 += e0 * v0.y; a2 += e0 * v1.x; a3 += e0 * v1.y;
                a4 += e0 * v2.x; a5 += e0 * v2.y; a6 += e0 * v3.x; a7 += e0 * v3.y;
            }
            {
                float2 v0 = __half22float2(*(__half2*)&h1.x);
                float2 v1 = __half22float2(*(__half2*)&h1.y);
                float2 v2 = __half22float2(*(__half2*)&h1.z);
                float2 v3 = __half22float2(*(__half2*)&h1.w);
                a0 += e1 * v0.x; a1 += e1 * v0.y; a2 += e1 * v1.x; a3 += e1 * v1.y;
                a4 += e1 * v2.x; a5 += e1 * v2.y; a6 += e1 * v3.x; a7 += e1 * v3.y;
            }
        }
        for (; j < cnt; j += 6) {             // leftover: up to 6 edges
            int je = j + g;
            bool valid = live && (je < cnt);
            int s = __shfl_sync(0xffffffffu, sv, je & 31);
            float tv = g_as2[s];
            uint4 h = *(const uint4*)((const uint4*)g_h2h + s * 5 + ti);
            float e = valid ? __expf(lrelu(tv + ad)) : 0.f;
            den += e;
            float2 v0 = __half22float2(*(__half2*)&h.x);
            float2 v1 = __half22float2(*(__half2*)&h.y);
            float2 v2 = __half22float2(*(__half2*)&h.z);
            float2 v3 = __half22float2(*(__half2*)&h.w);
            a0 += e * v0.x; a1 += e * v0.y; a2 += e * v1.x; a3 += e * v1.y;
            a4 += e * v2.x; a5 += e * v2.y; a6 += e * v3.x; a7 += e * v3.y;
        }
        k += cnt;
    }

    // tree-reduce 6 groups: lanes 0-14 pick up +15; lanes 0-4 pick up +5,+10
#define RED(X)                                                                   \
    {                                                                            \
        float w = __shfl_sync(0xffffffffu, X, (lane + 15) & 31); X += w;         \
        float u = __shfl_sync(0xffffffffu, X, (lane + 5) & 31);                  \
        float v = __shfl_sync(0xffffffffu, X, (lane + 10) & 31);                 \
        X += u + v;                                                              \
    }
    RED(den) RED(a0) RED(a1) RED(a2) RED(a3) RED(a4) RED(a5) RED(a6) RED(a7)
#undef RED

    if (lane < 5) {
        int c0 = lane * 8;
        float4 ba = *(const float4*)(b2 + c0);
        float4 bb = *(const float4*)(b2 + c0 + 4);
        float inv = 1.f / (den + 1e-16f);
        float4 r0, r1;
        r0.x = a0 * inv + ba.x; r0.y = a1 * inv + ba.y;
        r0.z = a2 * inv + ba.z; r0.w = a3 * inv + ba.w;
        r1.x = a4 * inv + bb.x; r1.y = a5 * inv + bb.y;
        r1.z = a6 * inv + bb.z; r1.w = a7 * inv + bb.w;
        *(float4*)(out + n * NCLS + c0)     = r0;
        *(float4*)(out + n * NCLS + c0 + 4) = r1;
    }
}

// ---------------- launch -----------------------------------------------------
extern "C" void kernel_launch(void* const* d_in, const int* in_sizes, int n_in,
                              void* d_out, int out_size) {
    const float* x   = (const float*)d_in[0];
    const void*  ei  = d_in[1];
    const float* W1  = (const float*)d_in[2];
    const float* as1 = (const float*)d_in[3];
    const float* ad1 = (const float*)d_in[4];
    const float* b1  = (const float*)d_in[5];
    const float* W2  = (const float*)d_in[6];
    const float* as2 = (const float*)d_in[7];
    const float* ad2 = (const float*)d_in[8];
    const float* b2  = (const float*)d_in[9];
    float*       out = (float*)d_out;

    // fork: CSR build on side stream, gemm1 concurrently on main stream
    cudaStream_t s1;
    cudaStreamCreateWithFlags(&s1, cudaStreamNonBlocking);
    cudaEvent_t ev0, ev1;
    cudaEventCreateWithFlags(&ev0, cudaEventDisableTiming);
    cudaEventCreateWithFlags(&ev1, cudaEventDisableTiming);

    cudaEventRecord(ev0, 0);
    cudaStreamWaitEvent(s1, ev0, 0);

    // ---- CSR build (side stream) ----
    probe_zero<<<(N_NODES + 256) / 256, 256, 0, s1>>>((const long long*)ei);
    hist_dst<<<((unsigned)TOT_E + 255) / 256, 256, 0, s1>>>(ei);
    scan_blocks<<<NB_SCAN, 1024, 0, s1>>>();
    fixup_offsets<<<(N_NODES + 256) / 256, 256, 0, s1>>>();
    scatter_csr<<<((unsigned)TOT_E + 255) / 256, 256, 0, s1>>>(ei);
    cudaEventRecord(ev1, s1);

    // ---- layer 1 GEMM (main stream, overlapped) ----
    gemm1<<<N_NODES / 32, 256>>>(x, W1, as1, ad1);

    // join
    cudaStreamWaitEvent(0, ev1, 0);

    // ---- layer 1 aggregation + fused layer-2 GEMM ----
    edge1_fused<<<(N_NODES + 7) / 8, 256>>>(b1, W2, as2, ad2);

    // ---- layer 2 ----
    edge_csr2<<<(N_NODES * 32 + 255) / 256, 256>>>(out, b2);

    cudaEventDestroy(ev0);
    cudaEventDestroy(ev1);
    cudaStreamDestroy(s1);
}

// round 9
// speedup vs baseline: 1.9357x; 1.0048x over previous
#include <cuda_runtime.h>
#include <cuda_fp16.h>

#define N_NODES 100000
#define N_EDGES 1600000
#define TOT_E   (N_EDGES + N_NODES)   // edges + self loops
#define F_IN    128
#define HEADS   8
#define HID     8
#define HC      64
#define NCLS    40
#define NEG_SLOPE 0.2f
#define NB_SCAN 98                     // ceil((N_NODES+1)/1024)

// ---------------- scratch (static device globals) ---------------------------
__device__ __align__(16) __half2 g_h1h[N_NODES * 32];   // layer1 features, fp16 pairs
__device__ __align__(8) __half2 g_e1[N_NODES * HEADS];  // (exp(as1), exp(.2 as1))
__device__ float g_ad1[N_NODES * HEADS];
__device__ __align__(16) __half2 g_h2h[N_NODES * 20];   // layer2 features, fp16 pairs
__device__ __half2 g_e2[N_NODES];                       // (exp(as2), exp(.2 as2))
__device__ float g_ad2[N_NODES];
__device__ int  g_csr_src[TOT_E];
__device__ int  g_deg[N_NODES + 1];
__device__ int  g_off[N_NODES + 1];
__device__ int  g_pos[N_NODES];
__device__ int  g_bsum[NB_SCAN];
__device__ int  g_is64;

// ---------------- probe dtype + zero degree array ---------------------------
__global__ void probe_zero(const long long* __restrict__ ei) {
    unsigned i = blockIdx.x * 256u + threadIdx.x;
    if (i <= N_NODES) g_deg[i] = 0;
    if (blockIdx.x == 0 && threadIdx.x < 32) {
        int l = threadIdx.x;
        int bad = 0;
#pragma unroll
        for (int k = 0; k < 8; k++) {
            long long v = ei[l * 8 + k];
            if (v < 0 || v >= (long long)N_NODES) bad = 1;
        }
        unsigned m = __ballot_sync(0xffffffffu, bad);
        if (l == 0) g_is64 = (m == 0u);
    }
}

__global__ void hist_dst(const void* __restrict__ ei) {
    unsigned e = blockIdx.x * 256u + threadIdx.x;
    if (e >= (unsigned)TOT_E) return;
    int d;
    if (e < (unsigned)N_EDGES) {
        d = g_is64 ? (int)((const long long*)ei)[N_EDGES + e]
                   : ((const int*)ei)[N_EDGES + e];
    } else {
        d = (int)(e - (unsigned)N_EDGES);
    }
    atomicAdd(&g_deg[d], 1);
}

__global__ void __launch_bounds__(1024) scan_blocks() {
    __shared__ int sh[1024];
    int t = threadIdx.x;
    unsigned i = blockIdx.x * 1024u + t;
    int v = (i <= N_NODES) ? g_deg[i] : 0;
    sh[t] = v; __syncthreads();
#pragma unroll
    for (int off = 1; off < 1024; off <<= 1) {
        int add = (t >= off) ? sh[t - off] : 0;
        __syncthreads();
        sh[t] += add;
        __syncthreads();
    }
    if (i <= N_NODES) g_off[i] = sh[t] - v;
    if (t == 1023) g_bsum[blockIdx.x] = sh[t];
}

__global__ void __launch_bounds__(256) fixup_offsets() {
    __shared__ int sb[128];
    int t = threadIdx.x;
    if (t < 128) sb[t] = (t < NB_SCAN) ? g_bsum[t] : 0;
    __syncthreads();
#pragma unroll
    for (int off = 1; off < 128; off <<= 1) {
        int add = (t < 128 && t >= off) ? sb[t - off] : 0;
        __syncthreads();
        if (t < 128) sb[t] += add;
        __syncthreads();
    }
    unsigned i = blockIdx.x * 256u + t;
    if (i > N_NODES) return;
    unsigned b = i >> 10;
    int pre = (b == 0) ? 0 : sb[b - 1];       // exclusive
    int o = g_off[i] + pre;
    g_off[i] = o;
    if (i < N_NODES) g_pos[i] = o;
}

__global__ void scatter_csr(const void* __restrict__ ei) {
    unsigned e = blockIdx.x * 256u + threadIdx.x;
    if (e >= (unsigned)TOT_E) return;
    int s, d;
    if (e < (unsigned)N_EDGES) {
        if (g_is64) {
            const long long* p = (const long long*)ei;
            s = (int)p[e]; d = (int)p[N_EDGES + e];
        } else {
            const int* p = (const int*)ei;
            s = p[e]; d = p[N_EDGES + e];
        }
    } else {
        s = d = (int)(e - (unsigned)N_EDGES);
    }
    int p = atomicAdd(&g_pos[d], 1);
    g_csr_src[p] = s;
}

// ---------------- layer 1 GEMM + attention logit exp tables -----------------
__global__ void __launch_bounds__(256) gemm1(const float* __restrict__ x,
                                             const float* __restrict__ W,
                                             const float* __restrict__ asrc,
                                             const float* __restrict__ adst) {
    __shared__ float  Ws[F_IN * HC];
    __shared__ float4 xs[8][F_IN];
    __shared__ float  as_s[HC], ad_s[HC];

    int tid = threadIdx.x;
    for (int i = tid; i < F_IN * HC; i += 256) Ws[i] = W[i];
    if (tid < HC) { as_s[tid] = asrc[tid]; ad_s[tid] = adst[tid]; }

    int warp = tid >> 5, lane = tid & 31;
    int n0 = blockIdx.x * 32 + warp * 4;

    for (int k = lane; k < F_IN; k += 32) {
        float4 v;
        v.x = x[(n0 + 0) * F_IN + k];
        v.y = x[(n0 + 1) * F_IN + k];
        v.z = x[(n0 + 2) * F_IN + k];
        v.w = x[(n0 + 3) * F_IN + k];
        xs[warp][k] = v;
    }
    __syncthreads();

    float a00 = 0, a01 = 0, a10 = 0, a11 = 0, a20 = 0, a21 = 0, a30 = 0, a31 = 0;
    const float2* W2p = (const float2*)Ws;
#pragma unroll 8
    for (int k = 0; k < F_IN; k++) {
        float4 xv = xs[warp][k];
        float2 wv = W2p[k * 32 + lane];
        a00 += xv.x * wv.x; a01 += xv.x * wv.y;
        a10 += xv.y * wv.x; a11 += xv.y * wv.y;
        a20 += xv.z * wv.x; a21 += xv.z * wv.y;
        a30 += xv.w * wv.x; a31 += xv.w * wv.y;
    }

    int j0 = lane * 2;
    float asx = as_s[j0], asy = as_s[j0 + 1];
    float adx = ad_s[j0], ady = ad_s[j0 + 1];

#define EMIT(E, A0, A1)                                                          \
    {                                                                            \
        int n = n0 + (E);                                                        \
        g_h1h[n * 32 + lane] = __floats2half2_rn((A0), (A1));                    \
        float ps = (A0) * asx + (A1) * asy;                                      \
        float pd = (A0) * adx + (A1) * ady;                                      \
        ps += __shfl_xor_sync(0xffffffffu, ps, 1);                               \
        ps += __shfl_xor_sync(0xffffffffu, ps, 2);                               \
        pd += __shfl_xor_sync(0xffffffffu, pd, 1);                               \
        pd += __shfl_xor_sync(0xffffffffu, pd, 2);                               \
        if ((lane & 3) == 0) {                                                   \
            int hh = lane >> 2;                                                  \
            g_e1[n * HEADS + hh] = __floats2half2_rn(__expf(ps),                 \
                                                     __expf(0.2f * ps));         \
            g_ad1[n * HEADS + hh] = pd;                                          \
        }                                                                        \
    }
    EMIT(0, a00, a01) EMIT(1, a10, a11) EMIT(2, a20, a21) EMIT(3, a30, a31)
#undef EMIT
}

// ---------------- layer 1 aggregation (table-based exp) + fused gemm2 -------
// Warp per node. Lane = slot p=lane>>3 x head q=lane&7.
// e = (Eps*Epd > 1) ? Eps*Epd : Ems*Emd  — no per-edge exp/lrelu.
__global__ void __launch_bounds__(256) edge1_fused(const float* __restrict__ b1,
                                                   const float* __restrict__ W2,
                                                   const float* __restrict__ as2v,
                                                   const float* __restrict__ ad2v) {
    __shared__ float Ws2[HC * NCLS];          // 10 KB
    __shared__ float a2s[NCLS], a2d[NCLS];
    __shared__ float hs[8][HC];

    int tid = threadIdx.x;
    for (int i = tid; i < HC * NCLS; i += 256) Ws2[i] = W2[i];
    if (tid < NCLS) { a2s[tid] = as2v[tid]; a2d[tid] = ad2v[tid]; }
    __syncthreads();

    int warp = tid >> 5, lane = tid & 31;
    int n = blockIdx.x * 8 + warp;
    if (n >= N_NODES) return;
    int q = lane & 7;                          // head
    int p = lane >> 3;                         // edge slot 0..3

    float ad  = g_ad1[n * 8 + q];
    float epd = __expf(ad);
    float emd = __expf(0.2f * ad);
    float den = 0.f;
    float a0 = 0.f, a1 = 0.f, a2 = 0.f, a3 = 0.f,
          a4 = 0.f, a5 = 0.f, a6 = 0.f, a7 = 0.f;

#define ACCUM(E, H)                                                              \
    {                                                                            \
        float2 v0 = __half22float2(*(__half2*)&(H).x);                           \
        float2 v1 = __half22float2(*(__half2*)&(H).y);                           \
        float2 v2 = __half22float2(*(__half2*)&(H).z);                           \
        float2 v3 = __half22float2(*(__half2*)&(H).w);                           \
        a0 += (E) * v0.x; a1 += (E) * v0.y; a2 += (E) * v1.x; a3 += (E) * v1.y;  \
        a4 += (E) * v2.x; a5 += (E) * v2.y; a6 += (E) * v3.x; a7 += (E) * v3.y;  \
    }

    int k = g_off[n], end = g_off[n + 1];
    while (k < end) {
        int cnt = min(32, end - k);
        int sv = (lane < cnt) ? g_csr_src[k + lane] : 0;
        int j = 0;
        for (; j + 16 <= cnt; j += 16) {      // 4 edges per lane, 16 per warp
            int s[4]; __half2 es[4]; uint4 h[4];
#pragma unroll
            for (int u = 0; u < 4; u++) s[u] = __shfl_sync(0xffffffffu, sv, j + 4 * u + p);
#pragma unroll
            for (int u = 0; u < 4; u++) {
                es[u] = g_e1[s[u] * 8 + q];
                h[u]  = *(const uint4*)(g_h1h + s[u] * 32 + q * 4);
            }
#pragma unroll
            for (int u = 0; u < 4; u++) {
                float2 ef = __half22float2(es[u]);
                float pe = ef.x * epd;
                float e = pe > 1.f ? pe : ef.y * emd;
                den += e;
                ACCUM(e, h[u])
            }
        }
        for (; j < cnt; j += 4) {             // leftover: up to 4 edges
            int je = j + p;
            bool valid = je < cnt;
            int s = __shfl_sync(0xffffffffu, sv, je & 31);
            __half2 es = g_e1[s * 8 + q];
            uint4 h = *(const uint4*)(g_h1h + s * 32 + q * 4);
            float2 ef = __half22float2(es);
            float pe = ef.x * epd;
            float e = valid ? (pe > 1.f ? pe : ef.y * emd) : 0.f;
            den += e;
            ACCUM(e, h)
        }
        k += cnt;
    }
#undef ACCUM

    // combine the 4 edge-slot groups (bits 3 and 4 of lane)
#define RED(X) X += __shfl_xor_sync(0xffffffffu, X, 8); X += __shfl_xor_sync(0xffffffffu, X, 16);
    RED(den) RED(a0) RED(a1) RED(a2) RED(a3) RED(a4) RED(a5) RED(a6) RED(a7)
#undef RED

    if (p == 0) {
        int c0 = q * 8;
        float4 ba = *(const float4*)(b1 + c0);
        float4 bb = *(const float4*)(b1 + c0 + 4);
        float inv = 1.f / (den + 1e-16f);
        hs[warp][c0]     = fmaxf(a0 * inv + ba.x, 0.f);
        hs[warp][c0 + 1] = fmaxf(a1 * inv + ba.y, 0.f);
        hs[warp][c0 + 2] = fmaxf(a2 * inv + ba.z, 0.f);
        hs[warp][c0 + 3] = fmaxf(a3 * inv + ba.w, 0.f);
        hs[warp][c0 + 4] = fmaxf(a4 * inv + bb.x, 0.f);
        hs[warp][c0 + 5] = fmaxf(a5 * inv + bb.y, 0.f);
        hs[warp][c0 + 6] = fmaxf(a6 * inv + bb.z, 0.f);
        hs[warp][c0 + 7] = fmaxf(a7 * inv + bb.w, 0.f);
    }
    __syncwarp();

    // ---- fused layer-2 GEMM: h2[n] = o1[n] @ W2, logits via warp reduce ----
    float acc0 = 0.f, acc1 = 0.f;
    int l8 = 32 + (lane & 7);
#pragma unroll 8
    for (int w = 0; w < HC; w++) {
        float hv = hs[warp][w];
        acc0 += hv * Ws2[w * NCLS + lane];
        acc1 += hv * Ws2[w * NCLS + l8];
    }

    __half* h2p = (__half*)g_h2h;
    h2p[n * NCLS + lane] = __float2half_rn(acc0);
    if (lane < 8) h2p[n * NCLS + 32 + lane] = __float2half_rn(acc1);

    float ps = acc0 * a2s[lane] + (lane < 8 ? acc1 * a2s[32 + lane] : 0.f);
    float pd = acc0 * a2d[lane] + (lane < 8 ? acc1 * a2d[32 + lane] : 0.f);
#pragma unroll
    for (int o = 16; o; o >>= 1) {
        ps += __shfl_xor_sync(0xffffffffu, ps, o);
        pd += __shfl_xor_sync(0xffffffffu, pd, o);
    }
    if (lane == 0) {
        g_e2[n] = __floats2half2_rn(__expf(ps), __expf(0.2f * ps));
        g_ad2[n] = pd;
    }
}

// ---------------- layer 2 CSR aggregation (table-based exp) ------------------
// 6 groups of 5 lanes; lane t owns classes [8t,8t+8) via one uint4.
__global__ void __launch_bounds__(256) edge_csr2(float* __restrict__ out,
                                                 const float* __restrict__ b2) {
    int warp = (blockIdx.x * 256 + threadIdx.x) >> 5;
    int lane = threadIdx.x & 31;
    if (warp >= N_NODES) return;
    int n = warp;
    int g = lane / 5;                          // group 0..5 (6 for lanes 30,31)
    int t = lane - g * 5;
    bool live = g < 6;
    int ti = live ? t : 0;

    float ad  = g_ad2[n];
    float epd = __expf(ad);
    float emd = __expf(0.2f * ad);
    float den = 0.f;
    float a0 = 0.f, a1 = 0.f, a2 = 0.f, a3 = 0.f,
          a4 = 0.f, a5 = 0.f, a6 = 0.f, a7 = 0.f;

#define ACCUM(E, H)                                                              \
    {                                                                            \
        float2 v0 = __half22float2(*(__half2*)&(H).x);                           \
        float2 v1 = __half22float2(*(__half2*)&(H).y);                           \
        float2 v2 = __half22float2(*(__half2*)&(H).z);                           \
        float2 v3 = __half22float2(*(__half2*)&(H).w);                           \
        a0 += (E) * v0.x; a1 += (E) * v0.y; a2 += (E) * v1.x; a3 += (E) * v1.y;  \
        a4 += (E) * v2.x; a5 += (E) * v2.y; a6 += (E) * v3.x; a7 += (E) * v3.y;  \
    }

    int k = g_off[n], end = g_off[n + 1];
    while (k < end) {
        int cnt = min(32, end - k);
        int sv = (lane < cnt) ? g_csr_src[k + lane] : 0;
        int j = 0;
        for (; j + 12 <= cnt; j += 12) {      // 2 edges per group, 12 per warp
            int s0 = __shfl_sync(0xffffffffu, sv, (j + g) & 31);
            int s1 = __shfl_sync(0xffffffffu, sv, (j + 6 + g) & 31);
            __half2 es0 = g_e2[s0];
            __half2 es1 = g_e2[s1];
            uint4 h0 = *(const uint4*)((const uint4*)g_h2h + s0 * 5 + ti);
            uint4 h1 = *(const uint4*)((const uint4*)g_h2h + s1 * 5 + ti);
            float2 ef0 = __half22float2(es0);
            float2 ef1 = __half22float2(es1);
            float pe0 = ef0.x * epd;
            float pe1 = ef1.x * epd;
            float e0 = live ? (pe0 > 1.f ? pe0 : ef0.y * emd) : 0.f;
            float e1 = live ? (pe1 > 1.f ? pe1 : ef1.y * emd) : 0.f;
            den += e0 + e1;
            ACCUM(e0, h0)
            ACCUM(e1, h1)
        }
        for (; j < cnt; j += 6) {             // leftover: up to 6 edges
            int je = j + g;
            bool valid = live && (je < cnt);
            int s = __shfl_sync(0xffffffffu, sv, je & 31);
            __half2 es = g_e2[s];
            uint4 h = *(const uint4*)((const uint4*)g_h2h + s * 5 + ti);
            float2 ef = __half22float2(es);
            float pe = ef.x * epd;
            float e = valid ? (pe > 1.f ? pe : ef.y * emd) : 0.f;
            den += e;
            ACCUM(e, h)
        }
        k += cnt;
    }
#undef ACCUM

    // tree-reduce 6 groups: lanes 0-14 pick up +15; lanes 0-4 pick up +5,+10
#define RED(X)                                                                   \
    {                                                                            \
        float w = __shfl_sync(0xffffffffu, X, (lane + 15) & 31); X += w;         \
        float u = __shfl_sync(0xffffffffu, X, (lane + 5) & 31);                  \
        float v = __shfl_sync(0xffffffffu, X, (lane + 10) & 31);                 \
        X += u + v;                                                              \
    }
    RED(den) RED(a0) RED(a1) RED(a2) RED(a3) RED(a4) RED(a5) RED(a6) RED(a7)
#undef RED

    if (lane < 5) {
        int c0 = lane * 8;
        float4 ba = *(const float4*)(b2 + c0);
        float4 bb = *(const float4*)(b2 + c0 + 4);
        float inv = 1.f / (den + 1e-16f);
        float4 r0, r1;
        r0.x = a0 * inv + ba.x; r0.y = a1 * inv + ba.y;
        r0.z = a2 * inv + ba.z; r0.w = a3 * inv + ba.w;
        r1.x = a4 * inv + bb.x; r1.y = a5 * inv + bb.y;
        r1.z = a6 * inv + bb.z; r1.w = a7 * inv + bb.w;
        *(float4*)(out + n * NCLS + c0)     = r0;
        *(float4*)(out + n * NCLS + c0 + 4) = r1;
    }
}

// ---------------- launch -----------------------------------------------------
extern "C" void kernel_launch(void* const* d_in, const int* in_sizes, int n_in,
                              void* d_out, int out_size) {
    const float* x   = (const float*)d_in[0];
    const void*  ei  = d_in[1];
    const float* W1  = (const float*)d_in[2];
    const float* as1 = (const float*)d_in[3];
    const float* ad1 = (const float*)d_in[4];
    const float* b1  = (const float*)d_in[5];
    const float* W2  = (const float*)d_in[6];
    const float* as2 = (const float*)d_in[7];
    const float* ad2 = (const float*)d_in[8];
    const float* b2  = (const float*)d_in[9];
    float*       out = (float*)d_out;

    // fork: CSR build on side stream, gemm1 concurrently on main stream
    cudaStream_t s1;
    cudaStreamCreateWithFlags(&s1, cudaStreamNonBlocking);
    cudaEvent_t ev0, ev1;
    cudaEventCreateWithFlags(&ev0, cudaEventDisableTiming);
    cudaEventCreateWithFlags(&ev1, cudaEventDisableTiming);

    cudaEventRecord(ev0, 0);
    cudaStreamWaitEvent(s1, ev0, 0);

    // ---- CSR build (side stream) ----
    probe_zero<<<(N_NODES + 256) / 256, 256, 0, s1>>>((const long long*)ei);
    hist_dst<<<((unsigned)TOT_E + 255) / 256, 256, 0, s1>>>(ei);
    scan_blocks<<<NB_SCAN, 1024, 0, s1>>>();
    fixup_offsets<<<(N_NODES + 256) / 256, 256, 0, s1>>>();
    scatter_csr<<<((unsigned)TOT_E + 255) / 256, 256, 0, s1>>>(ei);
    cudaEventRecord(ev1, s1);

    // ---- layer 1 GEMM (main stream, overlapped) ----
    gemm1<<<N_NODES / 32, 256>>>(x, W1, as1, ad1);

    // join
    cudaStreamWaitEvent(0, ev1, 0);

    // ---- layer 1 aggregation + fused layer-2 GEMM ----
    edge1_fused<<<(N_NODES + 7) / 8, 256>>>(b1, W2, as2, ad2);

    // ---- layer 2 ----
    edge_csr2<<<(N_NODES * 32 + 255) / 256, 256>>>(out, b2);

    cudaEventDestroy(ev0);
    cudaEventDestroy(ev1);
    cudaStreamDestroy(s1);
}